// round 3
// baseline (speedup 1.0000x reference)
#include <cuda_runtime.h>

#define T_TOKENS 4096
#define DIM      2048
#define NEXP     8
#define TOPK     2
#define HDIM     1024
#define HSDIM    2048
#define NSLOTS   (T_TOKENS * TOPK)

#define BM 128
#define BN 128
#define BKK 16
#define TM 8
#define TN 8
#define NTHREADS 256

// ---------------- scratch (device globals; no allocation allowed) ----------------
__device__ float g_hbuf[(size_t)NSLOTS * HDIM];    // routed h (weight-folded)  33.5 MB
__device__ float g_sh[(size_t)T_TOKENS * HSDIM];   // shared-expert h          33.5 MB
__device__ int   g_slot_token[NSLOTS];
__device__ float g_slot_w[NSLOTS];
__device__ int   g_counts[NEXP];
__device__ int   g_fill[NEXP];
__device__ int   g_offsets[NEXP + 1];
__device__ int   g_eidx[NSLOTS];
__device__ float g_topw[NSLOTS];

// ---------------- f32x2 packed-FMA helpers (Blackwell) ----------------
__device__ __forceinline__ double ffma2(double a, double b, double c) {
    double d;
    asm("fma.rn.f32x2 %0, %1, %2, %3;" : "=d"(d) : "d"(a), "d"(b), "d"(c));
    return d;
}
__device__ __forceinline__ double dup2(float a) {
    double d;
    asm("mov.b64 %0, {%1, %1};" : "=d"(d) : "f"(a));
    return d;
}
__device__ __forceinline__ float2 unpack2(double d) {
    float2 f;
    asm("mov.b64 {%0, %1}, %2;" : "=f"(f.x), "=f"(f.y) : "d"(d));
    return f;
}
__device__ __forceinline__ float silu_f(float g) {
    return g * (1.0f / (1.0f + __expf(-g)));
}

// ---------------- small kernels: routing ----------------
__global__ void zero_small_kernel() {
    int i = threadIdx.x;
    if (i < NEXP) { g_counts[i] = 0; g_fill[i] = 0; }
}

__global__ void router_kernel(const float* __restrict__ x, const float* __restrict__ rw) {
    int t = (blockIdx.x * blockDim.x + threadIdx.x) >> 5;
    int lane = threadIdx.x & 31;
    if (t >= T_TOKENS) return;
    const float* xr = x + (size_t)t * DIM;
    float lg[NEXP];
#pragma unroll
    for (int e = 0; e < NEXP; e++) lg[e] = 0.f;
    for (int d = lane; d < DIM; d += 32) {
        float xv = xr[d];
        const float* r = rw + (size_t)d * NEXP;
#pragma unroll
        for (int e = 0; e < NEXP; e++) lg[e] += xv * r[e];
    }
#pragma unroll
    for (int e = 0; e < NEXP; e++) {
#pragma unroll
        for (int o = 16; o; o >>= 1) lg[e] += __shfl_xor_sync(0xffffffffu, lg[e], o);
    }
    if (lane == 0) {
        float mx = lg[0];
#pragma unroll
        for (int e = 1; e < NEXP; e++) mx = fmaxf(mx, lg[e]);
        float p[NEXP];
#pragma unroll
        for (int e = 0; e < NEXP; e++) p[e] = __expf(lg[e] - mx);
        // top-2 (first-index wins ties, matching jax top_k)
        int i1 = 0;
#pragma unroll
        for (int e = 1; e < NEXP; e++) if (p[e] > p[i1]) i1 = e;
        int i2 = (i1 == 0) ? 1 : 0;
#pragma unroll
        for (int e = 0; e < NEXP; e++) if (e != i1 && p[e] > p[i2]) i2 = e;
        float w1 = p[i1], w2 = p[i2];
        float s = w1 + w2;
        w1 /= s; w2 /= s;
        g_eidx[2 * t] = i1; g_eidx[2 * t + 1] = i2;
        g_topw[2 * t] = w1; g_topw[2 * t + 1] = w2;
        atomicAdd(&g_counts[i1], 1);
        atomicAdd(&g_counts[i2], 1);
    }
}

__global__ void scan_kernel() {
    if (threadIdx.x == 0) {
        int acc = 0;
        for (int e = 0; e < NEXP; e++) { g_offsets[e] = acc; acc += g_counts[e]; }
        g_offsets[NEXP] = acc;
    }
}

__global__ void scatter_kernel() {
    int i = blockIdx.x * blockDim.x + threadIdx.x;
    if (i >= NSLOTS) return;
    int e = g_eidx[i];
    int pos = g_offsets[e] + atomicAdd(&g_fill[e], 1);
    g_slot_token[pos] = i >> 1;
    g_slot_w[pos] = g_topw[i];
}

// ---------------- fused gate/up GEMM (+SiLU) ----------------
// C[m,n] for two matmuls sharing A; epilogue h = silu(g)*u (* combine weight if ROUTED)
template <bool ROUTED>
__global__ __launch_bounds__(NTHREADS, 1)
void gateup_kernel(const float* __restrict__ X,
                   const float* __restrict__ Wg,
                   const float* __restrict__ Wu,
                   int N)  // HDIM (routed) or HSDIM (shared)
{
    int mtile = blockIdx.y, ntile = blockIdx.x;
    int expert = 0, start = 0, Me = T_TOKENS;
    if (ROUTED) {
        expert = blockIdx.z;
        start = g_offsets[expert];
        Me = g_offsets[expert + 1] - start;
        if (mtile * BM >= Me) return;
        Wg += (size_t)expert * DIM * N;
        Wu += (size_t)expert * DIM * N;
    }

    __shared__ float As[BKK][BM + 4];
    __shared__ float Bgs[BKK][BN];
    __shared__ float Bus[BKK][BN];

    int tid = threadIdx.x;
    int tx = tid & 15, ty = tid >> 4;

    // A loader: two rows per thread (rows tid/4 and tid/4+64), 4 cols each
    int arow0 = tid >> 2;
    int ac4 = (tid & 3) * 4;
    const float* arow_ptr[2];
#pragma unroll
    for (int it = 0; it < 2; it++) {
        int r = arow0 + it * 64;
        int rr = mtile * BM + r;
        if (rr >= Me) rr = Me - 1;              // clamp padding rows
        int gr = ROUTED ? g_slot_token[start + rr] : rr;
        arow_ptr[it] = X + (size_t)gr * DIM;
    }
    int brow0 = tid >> 5;
    int bc = (tid & 31) * 4;

    double accg[TM][TN / 2];
    double accu[TM][TN / 2];
#pragma unroll
    for (int i = 0; i < TM; i++)
#pragma unroll
        for (int j = 0; j < TN / 2; j++) { accg[i][j] = 0.0; accu[i][j] = 0.0; }

    for (int kt = 0; kt < DIM; kt += BKK) {
#pragma unroll
        for (int it = 0; it < 2; it++) {
            float4 v = *(const float4*)(arow_ptr[it] + kt + ac4);
            int r = arow0 + it * 64;
            As[ac4 + 0][r] = v.x; As[ac4 + 1][r] = v.y;
            As[ac4 + 2][r] = v.z; As[ac4 + 3][r] = v.w;
        }
#pragma unroll
        for (int it = 0; it < 2; it++) {
            int br = brow0 + it * 8;
            size_t off = (size_t)(kt + br) * N + (size_t)ntile * BN + bc;
            *(float4*)&Bgs[br][bc] = *(const float4*)(Wg + off);
            *(float4*)&Bus[br][bc] = *(const float4*)(Wu + off);
        }
        __syncthreads();
#pragma unroll
        for (int kk = 0; kk < BKK; kk++) {
            float a[TM];
            float4 a0 = *(const float4*)&As[kk][ty * TM];
            float4 a1 = *(const float4*)&As[kk][ty * TM + 4];
            a[0] = a0.x; a[1] = a0.y; a[2] = a0.z; a[3] = a0.w;
            a[4] = a1.x; a[5] = a1.y; a[6] = a1.z; a[7] = a1.w;
            double bg[4], bu[4];
            double2 g0 = *(const double2*)&Bgs[kk][tx * TN];
            double2 g1 = *(const double2*)&Bgs[kk][tx * TN + 4];
            bg[0] = g0.x; bg[1] = g0.y; bg[2] = g1.x; bg[3] = g1.y;
            double2 u0 = *(const double2*)&Bus[kk][tx * TN];
            double2 u1 = *(const double2*)&Bus[kk][tx * TN + 4];
            bu[0] = u0.x; bu[1] = u0.y; bu[2] = u1.x; bu[3] = u1.y;
#pragma unroll
            for (int i = 0; i < TM; i++) {
                double a2 = dup2(a[i]);
#pragma unroll
                for (int j = 0; j < TN / 2; j++) {
                    accg[i][j] = ffma2(a2, bg[j], accg[i][j]);
                    accu[i][j] = ffma2(a2, bu[j], accu[i][j]);
                }
            }
        }
        __syncthreads();
    }

    // epilogue
#pragma unroll
    for (int i = 0; i < TM; i++) {
        int rloc = ty * TM + i;
        int rglb = mtile * BM + rloc;
        if (ROUTED && rglb >= Me) continue;
        float w = 1.0f;
        float* orow;
        if (ROUTED) {
            int slot = start + rglb;
            w = g_slot_w[slot];
            orow = g_hbuf + (size_t)slot * N + (size_t)ntile * BN + tx * TN;
        } else {
            orow = g_sh + (size_t)rglb * N + (size_t)ntile * BN + tx * TN;
        }
#pragma unroll
        for (int j = 0; j < TN / 2; j++) {
            float2 g = unpack2(accg[i][j]);
            float2 u = unpack2(accu[i][j]);
            float2 h;
            h.x = silu_f(g.x) * u.x * w;
            h.y = silu_f(g.y) * u.y * w;
            *(float2*)&orow[2 * j] = h;
        }
    }
}

// ---------------- down-projection GEMM ----------------
// ROUTED: A = g_hbuf (by slot), epilogue atomicAdd into out[token].
// !ROUTED: A = g_sh (dense), epilogue plain store (initializes out).
template <bool ROUTED>
__global__ __launch_bounds__(NTHREADS, 1)
void down_kernel(const float* __restrict__ Wd,
                 float* __restrict__ Out,
                 int K)  // HDIM (routed) or HSDIM (shared)
{
    int mtile = blockIdx.y, ntile = blockIdx.x;
    int expert = 0, start = 0, Me = T_TOKENS;
    if (ROUTED) {
        expert = blockIdx.z;
        start = g_offsets[expert];
        Me = g_offsets[expert + 1] - start;
        if (mtile * BM >= Me) return;
        Wd += (size_t)expert * K * DIM;
    }
    const float* Abase = ROUTED ? g_hbuf : g_sh;

    __shared__ float As[BKK][BM + 4];
    __shared__ float Bs[BKK][BN];

    int tid = threadIdx.x;
    int tx = tid & 15, ty = tid >> 4;

    int arow0 = tid >> 2;
    int ac4 = (tid & 3) * 4;
    const float* arow_ptr[2];
#pragma unroll
    for (int it = 0; it < 2; it++) {
        int r = arow0 + it * 64;
        int rr = mtile * BM + r;
        if (rr >= Me) rr = Me - 1;
        size_t row = ROUTED ? (size_t)(start + rr) : (size_t)rr;
        arow_ptr[it] = Abase + row * K;
    }
    int brow0 = tid >> 5;
    int bc = (tid & 31) * 4;

    double acc[TM][TN / 2];
#pragma unroll
    for (int i = 0; i < TM; i++)
#pragma unroll
        for (int j = 0; j < TN / 2; j++) acc[i][j] = 0.0;

    for (int kt = 0; kt < K; kt += BKK) {
#pragma unroll
        for (int it = 0; it < 2; it++) {
            float4 v = *(const float4*)(arow_ptr[it] + kt + ac4);
            int r = arow0 + it * 64;
            As[ac4 + 0][r] = v.x; As[ac4 + 1][r] = v.y;
            As[ac4 + 2][r] = v.z; As[ac4 + 3][r] = v.w;
        }
#pragma unroll
        for (int it = 0; it < 2; it++) {
            int br = brow0 + it * 8;
            size_t off = (size_t)(kt + br) * DIM + (size_t)ntile * BN + bc;
            *(float4*)&Bs[br][bc] = *(const float4*)(Wd + off);
        }
        __syncthreads();
#pragma unroll
        for (int kk = 0; kk < BKK; kk++) {
            float a[TM];
            float4 a0 = *(const float4*)&As[kk][ty * TM];
            float4 a1 = *(const float4*)&As[kk][ty * TM + 4];
            a[0] = a0.x; a[1] = a0.y; a[2] = a0.z; a[3] = a0.w;
            a[4] = a1.x; a[5] = a1.y; a[6] = a1.z; a[7] = a1.w;
            double b[4];
            double2 b0 = *(const double2*)&Bs[kk][tx * TN];
            double2 b1 = *(const double2*)&Bs[kk][tx * TN + 4];
            b[0] = b0.x; b[1] = b0.y; b[2] = b1.x; b[3] = b1.y;
#pragma unroll
            for (int i = 0; i < TM; i++) {
                double a2 = dup2(a[i]);
#pragma unroll
                for (int j = 0; j < TN / 2; j++)
                    acc[i][j] = ffma2(a2, b[j], acc[i][j]);
            }
        }
        __syncthreads();
    }

    int colbase = ntile * BN + tx * TN;
#pragma unroll
    for (int i = 0; i < TM; i++) {
        int rloc = ty * TM + i;
        int rglb = mtile * BM + rloc;
        if (ROUTED) {
            if (rglb >= Me) continue;
            int token = g_slot_token[start + rglb];
            float* dst = Out + (size_t)token * DIM + colbase;
#pragma unroll
            for (int j = 0; j < TN / 2; j++) {
                float2 v = unpack2(acc[i][j]);
                atomicAdd(&dst[2 * j], v.x);
                atomicAdd(&dst[2 * j + 1], v.y);
            }
        } else {
            float* dst = Out + (size_t)rglb * DIM + colbase;
#pragma unroll
            for (int j = 0; j < TN / 2; j++) {
                float2 v = unpack2(acc[i][j]);
                *(float2*)&dst[2 * j] = v;
            }
        }
    }
}

// ---------------- launch ----------------
extern "C" void kernel_launch(void* const* d_in, const int* in_sizes, int n_in,
                              void* d_out, int out_size) {
    const float* x   = (const float*)d_in[0];
    const float* rw  = (const float*)d_in[1];
    const float* wg  = (const float*)d_in[2];
    const float* wu  = (const float*)d_in[3];
    const float* wd  = (const float*)d_in[4];
    const float* swg = (const float*)d_in[5];
    const float* swu = (const float*)d_in[6];
    const float* swd = (const float*)d_in[7];
    float* out = (float*)d_out;

    zero_small_kernel<<<1, 32>>>();
    router_kernel<<<T_TOKENS / 8, 256>>>(x, rw);
    scan_kernel<<<1, 32>>>();
    scatter_kernel<<<NSLOTS / 256, 256>>>();

    // shared expert: gate/up then down (down initializes out with plain stores)
    gateup_kernel<false><<<dim3(HSDIM / BN, T_TOKENS / BM, 1), NTHREADS>>>(x, swg, swu, HSDIM);
    down_kernel<false><<<dim3(DIM / BN, T_TOKENS / BM, 1), NTHREADS>>>(swd, out, HSDIM);

    // routed experts: grouped gate/up (gather + weight fold) then down (atomicAdd)
    gateup_kernel<true><<<dim3(HDIM / BN, NSLOTS / BM, NEXP), NTHREADS>>>(x, wg, wu, HDIM);
    down_kernel<true><<<dim3(DIM / BN, NSLOTS / BM, NEXP), NTHREADS>>>(wd, out, HDIM);
}

// round 5
// speedup vs baseline: 3.0758x; 3.0758x over previous
#include <cuda_runtime.h>
#include <cstdint>

#define T_TOKENS 4096
#define DIM      2048
#define NEXP     8
#define HDIM     1024
#define HSDIM    2048
#define NSLOTS   8192
#define PAD      128

// ---------------- scratch (device globals; no allocation allowed) ----------------
__device__ float g_xg[(size_t)(NSLOTS + PAD) * DIM];    // gathered+tf32-rounded x by slot
__device__ float g_xr[(size_t)T_TOKENS * DIM];          // tf32-rounded dense x
__device__ float g_hbuf[(size_t)(NSLOTS + PAD) * HDIM]; // routed h (weight-folded, rounded)
__device__ float g_sh[(size_t)T_TOKENS * HSDIM];        // shared-expert h (rounded)
__device__ int   g_slot_token[NSLOTS];
__device__ float g_slot_w[NSLOTS];
__device__ int   g_counts[NEXP];
__device__ int   g_fill[NEXP];
__device__ int   g_offsets[NEXP + 1];
__device__ int   g_eidx[NSLOTS];
__device__ float g_topw[NSLOTS];

// ---------------- helpers ----------------
__device__ __forceinline__ float rndt(float a) {
    float o; asm("cvt.rna.tf32.f32 %0, %1;" : "=f"(o) : "f"(a)); return o;
}
__device__ __forceinline__ uint32_t frt(float a) {  // round + bitcast
    float o; asm("cvt.rna.tf32.f32 %0, %1;" : "=f"(o) : "f"(a));
    return __float_as_uint(o);
}
__device__ __forceinline__ float silu_f(float g) {
    return g * (1.0f / (1.0f + __expf(-g)));
}
__device__ __forceinline__ uint32_t s2u(const void* p) {
    uint32_t a;
    asm("{ .reg .u64 t; cvta.to.shared.u64 t, %1; cvt.u32.u64 %0, t; }" : "=r"(a) : "l"(p));
    return a;
}
__device__ __forceinline__ void cp16(uint32_t s, const void* g) {
    asm volatile("cp.async.cg.shared.global [%0], [%1], 16;" :: "r"(s), "l"(g));
}
__device__ __forceinline__ void cp_commit() {
    asm volatile("cp.async.commit_group;" ::: "memory");
}
__device__ __forceinline__ void mma8(float* c, const uint32_t* a, const uint32_t* b) {
    asm volatile("mma.sync.aligned.m16n8k8.row.col.f32.tf32.tf32.f32 "
        "{%0,%1,%2,%3}, {%4,%5,%6,%7}, {%8,%9}, {%0,%1,%2,%3};"
        : "+f"(c[0]), "+f"(c[1]), "+f"(c[2]), "+f"(c[3])
        : "r"(a[0]), "r"(a[1]), "r"(a[2]), "r"(a[3]), "r"(b[0]), "r"(b[1]));
}

// SMEM tile geometry
#define ASTRIDE 20    // floats per A row (16 + 4 pad) -> conflict-free frag lds
#define BSTRIDE 136   // floats per B row (128 + 8 pad)
#define A_ST_BYTES (128 * ASTRIDE * 4)   // 10240
#define B_ST_BYTES (16 * BSTRIDE * 4)    // 8704
#define GU_SMEM (2 * A_ST_BYTES + 4 * B_ST_BYTES)  // 55296
#define DN_SMEM (2 * A_ST_BYTES + 2 * B_ST_BYTES)  // 37888

// ---------------- routing kernels ----------------
__global__ void zero_small_kernel() {
    int i = threadIdx.x;
    if (i < NEXP) { g_counts[i] = 0; g_fill[i] = 0; }
}

__global__ void router_kernel(const float* __restrict__ x, const float* __restrict__ rw) {
    int t = (blockIdx.x * blockDim.x + threadIdx.x) >> 5;
    int lane = threadIdx.x & 31;
    if (t >= T_TOKENS) return;
    const float* xr = x + (size_t)t * DIM;
    float lg[NEXP];
#pragma unroll
    for (int e = 0; e < NEXP; e++) lg[e] = 0.f;
    for (int d = lane; d < DIM; d += 32) {
        float xv = xr[d];
        const float* r = rw + (size_t)d * NEXP;
#pragma unroll
        for (int e = 0; e < NEXP; e++) lg[e] += xv * r[e];
    }
#pragma unroll
    for (int e = 0; e < NEXP; e++) {
#pragma unroll
        for (int o = 16; o; o >>= 1) lg[e] += __shfl_xor_sync(0xffffffffu, lg[e], o);
    }
    if (lane == 0) {
        float mx = lg[0];
#pragma unroll
        for (int e = 1; e < NEXP; e++) mx = fmaxf(mx, lg[e]);
        float p[NEXP];
#pragma unroll
        for (int e = 0; e < NEXP; e++) p[e] = __expf(lg[e] - mx);
        int i1 = 0;
#pragma unroll
        for (int e = 1; e < NEXP; e++) if (p[e] > p[i1]) i1 = e;
        int i2 = (i1 == 0) ? 1 : 0;
#pragma unroll
        for (int e = 0; e < NEXP; e++) if (e != i1 && p[e] > p[i2]) i2 = e;
        float w1 = p[i1], w2 = p[i2];
        float s = w1 + w2;
        w1 /= s; w2 /= s;
        g_eidx[2 * t] = i1; g_eidx[2 * t + 1] = i2;
        g_topw[2 * t] = w1; g_topw[2 * t + 1] = w2;
        atomicAdd(&g_counts[i1], 1);
        atomicAdd(&g_counts[i2], 1);
    }
}

__global__ void scan_kernel() {
    if (threadIdx.x == 0) {
        int acc = 0;
        for (int e = 0; e < NEXP; e++) { g_offsets[e] = acc; acc += g_counts[e]; }
        g_offsets[NEXP] = acc;
    }
}

__global__ void scatter_kernel() {
    int i = blockIdx.x * blockDim.x + threadIdx.x;
    if (i >= NSLOTS) return;
    int e = g_eidx[i];
    int pos = g_offsets[e] + atomicAdd(&g_fill[e], 1);
    g_slot_token[pos] = i >> 1;
    g_slot_w[pos] = g_topw[i];
}

// gather x rows into slot order (+zero pad) and make rounded dense copy
__global__ void gather_round_kernel(const float* __restrict__ x) {
    int row = blockIdx.x;
    int t = threadIdx.x;
    int c0 = t * 8;
    if (row < NSLOTS + PAD) {
        float* dst = g_xg + (size_t)row * DIM;
        if (row < NSLOTS) {
            const float* src = x + (size_t)g_slot_token[row] * DIM;
#pragma unroll
            for (int q = 0; q < 2; q++) {
                float4 v = *(const float4*)(src + c0 + q * 4);
                v.x = rndt(v.x); v.y = rndt(v.y); v.z = rndt(v.z); v.w = rndt(v.w);
                *(float4*)(dst + c0 + q * 4) = v;
            }
        } else {
            float4 z = make_float4(0.f, 0.f, 0.f, 0.f);
            *(float4*)(dst + c0) = z;
            *(float4*)(dst + c0 + 4) = z;
        }
    } else {
        int r = row - (NSLOTS + PAD);
        const float* src = x + (size_t)r * DIM;
        float* dst = g_xr + (size_t)r * DIM;
#pragma unroll
        for (int q = 0; q < 2; q++) {
            float4 v = *(const float4*)(src + c0 + q * 4);
            v.x = rndt(v.x); v.y = rndt(v.y); v.z = rndt(v.z); v.w = rndt(v.w);
            *(float4*)(dst + c0 + q * 4) = v;
        }
    }
}

// ---------------- fused gate/up GEMM via mma.sync tf32 ----------------
// Block tile 128(M)x128(N), BK=16, 512 threads = 16 warps (4x4), warp tile 32x32.
// A (x) pre-rounded; B (weights, natural [k][n] layout) rounded per-fragment.
template <bool ROUTED>
__global__ __launch_bounds__(512, 1)
void gateup_mma(const float* __restrict__ Wg, const float* __restrict__ Wu) {
    extern __shared__ char smem[];
    constexpr int N = ROUTED ? HDIM : HSDIM;
    constexpr int KT = DIM / 16;  // 128
    float* As = (float*)smem;                              // [2][128*20]
    float* Bgs = (float*)(smem + 2 * A_ST_BYTES);          // [2][16*136]
    float* Bus = (float*)(smem + 2 * A_ST_BYTES + 2 * B_ST_BYTES);
    uint32_t smA = s2u(smem);
    uint32_t smBg = smA + 2 * A_ST_BYTES;
    uint32_t smBu = smBg + 2 * B_ST_BYTES;

    int tid = threadIdx.x, wid = tid >> 5, lane = tid & 31;
    int warpM = (wid >> 2) * 32, warpN = (wid & 3) * 32;
    int gl = lane >> 2, kl = lane & 3;
    int ntile = blockIdx.x, mtile = blockIdx.y;

    int start = 0, Me = T_TOKENS;
    if (ROUTED) {
        int expert = blockIdx.z;
        start = g_offsets[expert];
        Me = g_offsets[expert + 1] - start;
        if (mtile * 128 >= Me) return;
        Wg += (size_t)expert * DIM * HDIM;
        Wu += (size_t)expert * DIM * HDIM;
    }
    const float* Abase = (ROUTED ? g_xg : g_xr) + (size_t)(start + mtile * 128) * DIM;

    // copy lanes
    int arow = tid >> 2, ac4 = (tid & 3) * 4;
    const float* pA = Abase + (size_t)arow * DIM + ac4;
    uint32_t dA = smA + (arow * ASTRIDE + ac4) * 4;
    int brow = tid >> 5, bc4 = (tid & 31) * 4;
    const float* pBg = Wg + (size_t)brow * N + (size_t)ntile * 128 + bc4;
    const float* pBu = Wu + (size_t)brow * N + (size_t)ntile * 128 + bc4;
    uint32_t dB = (brow * BSTRIDE + bc4) * 4;

#define GU_COPY(stg, kt) do { \
    cp16(dA + (stg) * A_ST_BYTES, pA + (kt) * 16); \
    cp16(smBg + (stg) * B_ST_BYTES + dB, pBg + (size_t)(kt) * 16 * N); \
    cp16(smBu + (stg) * B_ST_BYTES + dB, pBu + (size_t)(kt) * 16 * N); \
    cp_commit(); \
} while (0)

    float ag[2][4][4], au[2][4][4];
#pragma unroll
    for (int mm = 0; mm < 2; mm++)
#pragma unroll
        for (int nn = 0; nn < 4; nn++)
#pragma unroll
            for (int q = 0; q < 4; q++) { ag[mm][nn][q] = 0.f; au[mm][nn][q] = 0.f; }

    GU_COPY(0, 0);
    for (int kt = 0; kt < KT; kt++) {
        int cur = kt & 1;
        if (kt + 1 < KT) {
            GU_COPY(cur ^ 1, kt + 1);
            asm volatile("cp.async.wait_group 1;" ::: "memory");
        } else {
            asm volatile("cp.async.wait_group 0;" ::: "memory");
        }
        __syncthreads();
        const float* as = As + cur * (A_ST_BYTES / 4);
        const float* bg = Bgs + cur * (B_ST_BYTES / 4);
        const float* bu = Bus + cur * (B_ST_BYTES / 4);
#pragma unroll
        for (int ks = 0; ks < 16; ks += 8) {
            uint32_t a[2][4];
#pragma unroll
            for (int mm = 0; mm < 2; mm++) {
                int r = warpM + mm * 16 + gl;
                a[mm][0] = __float_as_uint(as[r * ASTRIDE + ks + kl]);
                a[mm][1] = __float_as_uint(as[(r + 8) * ASTRIDE + ks + kl]);
                a[mm][2] = __float_as_uint(as[r * ASTRIDE + ks + kl + 4]);
                a[mm][3] = __float_as_uint(as[(r + 8) * ASTRIDE + ks + kl + 4]);
            }
            uint32_t bgf[4][2], buf[4][2];
#pragma unroll
            for (int nn = 0; nn < 4; nn++) {
                int c = warpN + nn * 8 + gl;
                bgf[nn][0] = frt(bg[(ks + kl) * BSTRIDE + c]);
                bgf[nn][1] = frt(bg[(ks + kl + 4) * BSTRIDE + c]);
                buf[nn][0] = frt(bu[(ks + kl) * BSTRIDE + c]);
                buf[nn][1] = frt(bu[(ks + kl + 4) * BSTRIDE + c]);
            }
#pragma unroll
            for (int mm = 0; mm < 2; mm++)
#pragma unroll
                for (int nn = 0; nn < 4; nn++) {
                    mma8(ag[mm][nn], a[mm], bgf[nn]);
                    mma8(au[mm][nn], a[mm], buf[nn]);
                }
        }
        __syncthreads();
    }

    // epilogue: h = round(silu(g)*u*w)
#pragma unroll
    for (int mm = 0; mm < 2; mm++) {
#pragma unroll
        for (int half = 0; half < 2; half++) {
            int rglb = mtile * 128 + warpM + mm * 16 + gl + half * 8;
            bool live = (!ROUTED) || (rglb < Me);
            if (!live) continue;
            float w = 1.0f;
            float* dst;
            if (ROUTED) {
                int slot = start + rglb;
                w = g_slot_w[slot];
                dst = g_hbuf + (size_t)slot * HDIM + (size_t)ntile * 128;
            } else {
                dst = g_sh + (size_t)rglb * HSDIM + (size_t)ntile * 128;
            }
#pragma unroll
            for (int nn = 0; nn < 4; nn++) {
                int c = warpN + nn * 8 + 2 * kl;
                float gv0 = ag[mm][nn][half * 2], gv1 = ag[mm][nn][half * 2 + 1];
                float uv0 = au[mm][nn][half * 2], uv1 = au[mm][nn][half * 2 + 1];
                float2 h;
                h.x = rndt(silu_f(gv0) * uv0 * w);
                h.y = rndt(silu_f(gv1) * uv1 * w);
                *(float2*)(dst + c) = h;
            }
        }
    }
}

// ---------------- down GEMM via mma.sync tf32 ----------------
template <bool ROUTED>
__global__ __launch_bounds__(512, 1)
void down_mma(const float* __restrict__ Wd, float* __restrict__ Out) {
    extern __shared__ char smem[];
    constexpr int K = ROUTED ? HDIM : HSDIM;
    constexpr int KT = K / 16;
    float* As = (float*)smem;
    float* Bs = (float*)(smem + 2 * A_ST_BYTES);
    uint32_t smA = s2u(smem);
    uint32_t smB = smA + 2 * A_ST_BYTES;

    int tid = threadIdx.x, wid = tid >> 5, lane = tid & 31;
    int warpM = (wid >> 2) * 32, warpN = (wid & 3) * 32;
    int gl = lane >> 2, kl = lane & 3;
    int ntile = blockIdx.x, mtile = blockIdx.y;

    int start = 0, Me = T_TOKENS;
    if (ROUTED) {
        int expert = blockIdx.z;
        start = g_offsets[expert];
        Me = g_offsets[expert + 1] - start;
        if (mtile * 128 >= Me) return;
        Wd += (size_t)expert * HDIM * DIM;
    }
    const float* Abase = (ROUTED ? g_hbuf : g_sh) + (size_t)(start + mtile * 128) * K;

    int arow = tid >> 2, ac4 = (tid & 3) * 4;
    const float* pA = Abase + (size_t)arow * K + ac4;
    uint32_t dA = smA + (arow * ASTRIDE + ac4) * 4;
    int brow = tid >> 5, bc4 = (tid & 31) * 4;
    const float* pB = Wd + (size_t)brow * DIM + (size_t)ntile * 128 + bc4;
    uint32_t dB = smB + (brow * BSTRIDE + bc4) * 4;

#define DN_COPY(stg, kt) do { \
    cp16(dA + (stg) * A_ST_BYTES, pA + (kt) * 16); \
    cp16(dB + (stg) * B_ST_BYTES, pB + (size_t)(kt) * 16 * DIM); \
    cp_commit(); \
} while (0)

    float acc[2][4][4];
#pragma unroll
    for (int mm = 0; mm < 2; mm++)
#pragma unroll
        for (int nn = 0; nn < 4; nn++)
#pragma unroll
            for (int q = 0; q < 4; q++) acc[mm][nn][q] = 0.f;

    DN_COPY(0, 0);
    for (int kt = 0; kt < KT; kt++) {
        int cur = kt & 1;
        if (kt + 1 < KT) {
            DN_COPY(cur ^ 1, kt + 1);
            asm volatile("cp.async.wait_group 1;" ::: "memory");
        } else {
            asm volatile("cp.async.wait_group 0;" ::: "memory");
        }
        __syncthreads();
        const float* as = As + cur * (A_ST_BYTES / 4);
        const float* bs = Bs + cur * (B_ST_BYTES / 4);
#pragma unroll
        for (int ks = 0; ks < 16; ks += 8) {
            uint32_t a[2][4];
#pragma unroll
            for (int mm = 0; mm < 2; mm++) {
                int r = warpM + mm * 16 + gl;
                a[mm][0] = __float_as_uint(as[r * ASTRIDE + ks + kl]);
                a[mm][1] = __float_as_uint(as[(r + 8) * ASTRIDE + ks + kl]);
                a[mm][2] = __float_as_uint(as[r * ASTRIDE + ks + kl + 4]);
                a[mm][3] = __float_as_uint(as[(r + 8) * ASTRIDE + ks + kl + 4]);
            }
            uint32_t bf[4][2];
#pragma unroll
            for (int nn = 0; nn < 4; nn++) {
                int c = warpN + nn * 8 + gl;
                bf[nn][0] = frt(bs[(ks + kl) * BSTRIDE + c]);
                bf[nn][1] = frt(bs[(ks + kl + 4) * BSTRIDE + c]);
            }
#pragma unroll
            for (int mm = 0; mm < 2; mm++)
#pragma unroll
                for (int nn = 0; nn < 4; nn++)
                    mma8(acc[mm][nn], a[mm], bf[nn]);
        }
        __syncthreads();
    }

#pragma unroll
    for (int mm = 0; mm < 2; mm++) {
#pragma unroll
        for (int half = 0; half < 2; half++) {
            int rglb = mtile * 128 + warpM + mm * 16 + gl + half * 8;
            bool live = (!ROUTED) || (rglb < Me);
            if (!live) continue;
            float* dst;
            if (ROUTED) {
                int token = g_slot_token[start + rglb];
                dst = Out + (size_t)token * DIM + (size_t)ntile * 128;
            } else {
                dst = Out + (size_t)rglb * DIM + (size_t)ntile * 128;
            }
#pragma unroll
            for (int nn = 0; nn < 4; nn++) {
                int c = warpN + nn * 8 + 2 * kl;
                float v0 = acc[mm][nn][half * 2], v1 = acc[mm][nn][half * 2 + 1];
                if (ROUTED) {
                    atomicAdd(dst + c, v0);
                    atomicAdd(dst + c + 1, v1);
                } else {
                    float2 v; v.x = v0; v.y = v1;
                    *(float2*)(dst + c) = v;
                }
            }
        }
    }
}

// ---------------- launch ----------------
extern "C" void kernel_launch(void* const* d_in, const int* in_sizes, int n_in,
                              void* d_out, int out_size) {
    const float* x   = (const float*)d_in[0];
    const float* rw  = (const float*)d_in[1];
    const float* wg  = (const float*)d_in[2];
    const float* wu  = (const float*)d_in[3];
    const float* wd  = (const float*)d_in[4];
    const float* swg = (const float*)d_in[5];
    const float* swu = (const float*)d_in[6];
    const float* swd = (const float*)d_in[7];
    float* out = (float*)d_out;

    cudaFuncSetAttribute(gateup_mma<false>, cudaFuncAttributeMaxDynamicSharedMemorySize, GU_SMEM);
    cudaFuncSetAttribute(gateup_mma<true>,  cudaFuncAttributeMaxDynamicSharedMemorySize, GU_SMEM);
    cudaFuncSetAttribute(down_mma<false>,   cudaFuncAttributeMaxDynamicSharedMemorySize, DN_SMEM);
    cudaFuncSetAttribute(down_mma<true>,    cudaFuncAttributeMaxDynamicSharedMemorySize, DN_SMEM);

    zero_small_kernel<<<1, 32>>>();
    router_kernel<<<T_TOKENS / 8, 256>>>(x, rw);
    scan_kernel<<<1, 32>>>();
    scatter_kernel<<<NSLOTS / 256, 256>>>();
    gather_round_kernel<<<NSLOTS + PAD + T_TOKENS, 256>>>(x);

    // shared expert
    gateup_mma<false><<<dim3(HSDIM / 128, T_TOKENS / 128, 1), 512, GU_SMEM>>>(swg, swu);
    down_mma<false><<<dim3(DIM / 128, T_TOKENS / 128, 1), 512, DN_SMEM>>>(swd, out);
    // routed experts
    gateup_mma<true><<<dim3(HDIM / 128, NSLOTS / 128, NEXP), 512, GU_SMEM>>>(wg, wu);
    down_mma<true><<<dim3(DIM / 128, NSLOTS / 128, NEXP), 512, DN_SMEM>>>(wd, out);
}

// round 6
// speedup vs baseline: 5.0007x; 1.6259x over previous
#include <cuda_runtime.h>
#include <cuda_fp16.h>
#include <cstdint>

#define T_TOKENS 4096
#define DIM      2048
#define NEXP     8
#define HDIM     1024
#define HSDIM    2048
#define NSLOTS   8192
#define PAD      128

// ---------------- scratch (device globals; no allocation allowed) ----------------
__device__ __half g_xg[(size_t)(NSLOTS + PAD) * DIM];    // gathered fp16 x by slot
__device__ __half g_xr[(size_t)T_TOKENS * DIM];          // fp16 dense x
__device__ __half g_hbuf[(size_t)(NSLOTS + PAD) * HDIM]; // routed h (weight-folded)
__device__ __half g_sh[(size_t)T_TOKENS * HSDIM];        // shared-expert h
__device__ __half g_wgh[(size_t)NEXP * DIM * HDIM];      // interleaved [K/2][N][2]
__device__ __half g_wuh[(size_t)NEXP * DIM * HDIM];
__device__ __half g_wdh[(size_t)NEXP * HDIM * DIM];
__device__ __half g_swgh[(size_t)DIM * HSDIM];
__device__ __half g_swuh[(size_t)DIM * HSDIM];
__device__ __half g_swdh[(size_t)HSDIM * DIM];
__device__ int   g_slot_token[NSLOTS];
__device__ float g_slot_w[NSLOTS];
__device__ int   g_counts[NEXP];
__device__ int   g_fill[NEXP];
__device__ int   g_offsets[NEXP + 1];
__device__ int   g_eidx[NSLOTS];
__device__ float g_topw[NSLOTS];

// ---------------- helpers ----------------
__device__ __forceinline__ float silu_f(float g) {
    return g * (1.0f / (1.0f + __expf(-g)));
}
__device__ __forceinline__ uint32_t s2u(const void* p) {
    uint32_t a;
    asm("{ .reg .u64 t; cvta.to.shared.u64 t, %1; cvt.u32.u64 %0, t; }" : "=r"(a) : "l"(p));
    return a;
}
__device__ __forceinline__ void cp16(uint32_t s, const void* g) {
    asm volatile("cp.async.cg.shared.global [%0], [%1], 16;" :: "r"(s), "l"(g));
}
__device__ __forceinline__ void cp_commit() {
    asm volatile("cp.async.commit_group;" ::: "memory");
}
__device__ __forceinline__ void mma16(float* c, const uint32_t* a, const uint32_t* b) {
    asm volatile("mma.sync.aligned.m16n8k16.row.col.f32.f16.f16.f32 "
        "{%0,%1,%2,%3}, {%4,%5,%6,%7}, {%8,%9}, {%0,%1,%2,%3};"
        : "+f"(c[0]), "+f"(c[1]), "+f"(c[2]), "+f"(c[3])
        : "r"(a[0]), "r"(a[1]), "r"(a[2]), "r"(a[3]), "r"(b[0]), "r"(b[1]));
}

// SMEM geometry (fp16)
#define AST 40        // halves per A smem row (32 + 8 pad) -> conflict-free b32 lds
#define BSTP 136      // pairs per B smem k2-row (128 + 8 pad)
#define A_ST_BYTES (128 * AST * 2)    // 10240
#define B_ST_BYTES (16 * BSTP * 4)    // 8704
#define GU_SMEM (2 * (A_ST_BYTES + 2 * B_ST_BYTES))  // 55296
#define DN_SMEM (2 * (A_ST_BYTES + B_ST_BYTES))      // 37888

// ---------------- routing kernels ----------------
__global__ void zero_small_kernel() {
    int i = threadIdx.x;
    if (i < NEXP) { g_counts[i] = 0; g_fill[i] = 0; }
}

__global__ void router_kernel(const float* __restrict__ x, const float* __restrict__ rw) {
    int t = (blockIdx.x * blockDim.x + threadIdx.x) >> 5;
    int lane = threadIdx.x & 31;
    if (t >= T_TOKENS) return;
    const float* xr = x + (size_t)t * DIM;
    float lg[NEXP];
#pragma unroll
    for (int e = 0; e < NEXP; e++) lg[e] = 0.f;
    for (int d = lane; d < DIM; d += 32) {
        float xv = xr[d];
        const float* r = rw + (size_t)d * NEXP;
#pragma unroll
        for (int e = 0; e < NEXP; e++) lg[e] += xv * r[e];
    }
#pragma unroll
    for (int e = 0; e < NEXP; e++) {
#pragma unroll
        for (int o = 16; o; o >>= 1) lg[e] += __shfl_xor_sync(0xffffffffu, lg[e], o);
    }
    if (lane == 0) {
        float mx = lg[0];
#pragma unroll
        for (int e = 1; e < NEXP; e++) mx = fmaxf(mx, lg[e]);
        float p[NEXP];
#pragma unroll
        for (int e = 0; e < NEXP; e++) p[e] = __expf(lg[e] - mx);
        int i1 = 0;
#pragma unroll
        for (int e = 1; e < NEXP; e++) if (p[e] > p[i1]) i1 = e;
        int i2 = (i1 == 0) ? 1 : 0;
#pragma unroll
        for (int e = 0; e < NEXP; e++) if (e != i1 && p[e] > p[i2]) i2 = e;
        float w1 = p[i1], w2 = p[i2];
        float s = w1 + w2;
        w1 /= s; w2 /= s;
        g_eidx[2 * t] = i1; g_eidx[2 * t + 1] = i2;
        g_topw[2 * t] = w1; g_topw[2 * t + 1] = w2;
        atomicAdd(&g_counts[i1], 1);
        atomicAdd(&g_counts[i2], 1);
    }
}

__global__ void scan_kernel() {
    if (threadIdx.x == 0) {
        int acc = 0;
        for (int e = 0; e < NEXP; e++) { g_offsets[e] = acc; acc += g_counts[e]; }
        g_offsets[NEXP] = acc;
    }
}

__global__ void scatter_kernel() {
    int i = blockIdx.x * blockDim.x + threadIdx.x;
    if (i >= NSLOTS) return;
    int e = g_eidx[i];
    int pos = g_offsets[e] + atomicAdd(&g_fill[e], 1);
    g_slot_token[pos] = i >> 1;
    g_slot_w[pos] = g_topw[i];
}

// ---------------- weight fp32 [K][N] -> fp16 interleaved [K/2][N][2] ----------------
__global__ void convw_kernel(const float* __restrict__ src, __half* __restrict__ dst,
                             int K, int N) {
    int npack = N >> 2;
    int idx = blockIdx.x * 256 + threadIdx.x;
    if (idx >= (K >> 1) * npack) return;
    int k2 = idx / npack, n0 = (idx - k2 * npack) * 4;
    const float* r0 = src + (size_t)(2 * k2) * N + n0;
    const float* r1 = r0 + N;
    float4 a = *(const float4*)r0;
    float4 b = *(const float4*)r1;
    __half h[8];
    h[0] = __float2half(a.x); h[1] = __float2half(b.x);
    h[2] = __float2half(a.y); h[3] = __float2half(b.y);
    h[4] = __float2half(a.z); h[5] = __float2half(b.z);
    h[6] = __float2half(a.w); h[7] = __float2half(b.w);
    *(uint4*)(dst + ((size_t)k2 * N + n0) * 2) = *(uint4*)h;
}

// gather x rows into slot order (fp16, +zero pad) and dense fp16 copy
__global__ void gather_half_kernel(const float* __restrict__ x) {
    int row = blockIdx.x;
    int c0 = threadIdx.x * 8;
    __half h[8];
    if (row < NSLOTS + PAD) {
        __half* dst = g_xg + (size_t)row * DIM;
        if (row < NSLOTS) {
            const float* src = x + (size_t)g_slot_token[row] * DIM;
            float4 v0 = *(const float4*)(src + c0);
            float4 v1 = *(const float4*)(src + c0 + 4);
            h[0] = __float2half(v0.x); h[1] = __float2half(v0.y);
            h[2] = __float2half(v0.z); h[3] = __float2half(v0.w);
            h[4] = __float2half(v1.x); h[5] = __float2half(v1.y);
            h[6] = __float2half(v1.z); h[7] = __float2half(v1.w);
        } else {
#pragma unroll
            for (int q = 0; q < 8; q++) h[q] = __float2half(0.f);
        }
        *(uint4*)(dst + c0) = *(uint4*)h;
    } else {
        int r = row - (NSLOTS + PAD);
        const float* src = x + (size_t)r * DIM;
        float4 v0 = *(const float4*)(src + c0);
        float4 v1 = *(const float4*)(src + c0 + 4);
        h[0] = __float2half(v0.x); h[1] = __float2half(v0.y);
        h[2] = __float2half(v0.z); h[3] = __float2half(v0.w);
        h[4] = __float2half(v1.x); h[5] = __float2half(v1.y);
        h[6] = __float2half(v1.z); h[7] = __float2half(v1.w);
        *(uint4*)(g_xr + (size_t)r * DIM + c0) = *(uint4*)h;
    }
}

// ---------------- fused gate/up GEMM via mma.sync fp16 ----------------
// Block 128x128, BK=32, 512 threads (16 warps 4x4), warp tile 32x32.
template <bool ROUTED>
__global__ __launch_bounds__(512, 1)
void gateup_mma(const __half* __restrict__ Wg, const __half* __restrict__ Wu) {
    extern __shared__ char smem[];
    constexpr int N = ROUTED ? HDIM : HSDIM;
    constexpr int KT = DIM / 32;  // 64
    uint32_t smA = s2u(smem);
    uint32_t smBg = smA + 2 * A_ST_BYTES;
    uint32_t smBu = smBg + 2 * B_ST_BYTES;

    int tid = threadIdx.x, wid = tid >> 5, lane = tid & 31;
    int warpM = (wid >> 2) * 32, warpN = (wid & 3) * 32;
    int gl = lane >> 2, kl = lane & 3;
    int ntile = blockIdx.x, mtile = blockIdx.y;

    int start = 0, Me = T_TOKENS;
    if (ROUTED) {
        int expert = blockIdx.z;
        start = g_offsets[expert];
        Me = g_offsets[expert + 1] - start;
        if (mtile * 128 >= Me) return;
        Wg += (size_t)expert * DIM * HDIM;
        Wu += (size_t)expert * DIM * HDIM;
    }
    const __half* Abase = (ROUTED ? g_xg : g_xr) + (size_t)(start + mtile * 128) * DIM;

    // copy lanes: A 1x cp16/thread, B 1x cp16/thread per matrix
    int arow = tid >> 2, ac = (tid & 3) * 8;
    const __half* pA = Abase + (size_t)arow * DIM + ac;
    uint32_t dA = smA + (arow * AST + ac) * 2;
    int brw = tid >> 5, bc4 = (tid & 31) * 4;
    const __half* pBg = Wg + ((size_t)brw * N + (size_t)ntile * 128 + bc4) * 2;
    const __half* pBu = Wu + ((size_t)brw * N + (size_t)ntile * 128 + bc4) * 2;
    uint32_t dB = (brw * BSTP + bc4) * 4;

#define GU_COPY(stg, kt) do { \
    cp16(dA + (stg) * A_ST_BYTES, pA + (kt) * 32); \
    cp16(smBg + (stg) * B_ST_BYTES + dB, pBg + (size_t)(kt) * 16 * N * 2); \
    cp16(smBu + (stg) * B_ST_BYTES + dB, pBu + (size_t)(kt) * 16 * N * 2); \
    cp_commit(); \
} while (0)

    float ag[2][4][4], au[2][4][4];
#pragma unroll
    for (int mm = 0; mm < 2; mm++)
#pragma unroll
        for (int nn = 0; nn < 4; nn++)
#pragma unroll
            for (int q = 0; q < 4; q++) { ag[mm][nn][q] = 0.f; au[mm][nn][q] = 0.f; }

    GU_COPY(0, 0);
    for (int kt = 0; kt < KT; kt++) {
        int cur = kt & 1;
        if (kt + 1 < KT) {
            GU_COPY(cur ^ 1, kt + 1);
            asm volatile("cp.async.wait_group 1;" ::: "memory");
        } else {
            asm volatile("cp.async.wait_group 0;" ::: "memory");
        }
        __syncthreads();
        const uint32_t* as = (const uint32_t*)(smem + cur * A_ST_BYTES);
        const uint32_t* bg = (const uint32_t*)(smem + 2 * A_ST_BYTES + cur * B_ST_BYTES);
        const uint32_t* bu = (const uint32_t*)(smem + 2 * A_ST_BYTES + 2 * B_ST_BYTES
                                               + cur * B_ST_BYTES);
#pragma unroll
        for (int ks2 = 0; ks2 < 16; ks2 += 8) {   // ks2 = k/2 offset (k=0,16)
            uint32_t a[2][4];
#pragma unroll
            for (int mm = 0; mm < 2; mm++) {
                int r = warpM + mm * 16 + gl;
                a[mm][0] = as[r * 20 + ks2 + kl];
                a[mm][1] = as[(r + 8) * 20 + ks2 + kl];
                a[mm][2] = as[r * 20 + ks2 + kl + 4];
                a[mm][3] = as[(r + 8) * 20 + ks2 + kl + 4];
            }
            uint32_t bgf[4][2], buf[4][2];
#pragma unroll
            for (int nn = 0; nn < 4; nn++) {
                int c = warpN + nn * 8 + gl;
                bgf[nn][0] = bg[(ks2 + kl) * BSTP + c];
                bgf[nn][1] = bg[(ks2 + kl + 4) * BSTP + c];
                buf[nn][0] = bu[(ks2 + kl) * BSTP + c];
                buf[nn][1] = bu[(ks2 + kl + 4) * BSTP + c];
            }
#pragma unroll
            for (int mm = 0; mm < 2; mm++)
#pragma unroll
                for (int nn = 0; nn < 4; nn++) {
                    mma16(ag[mm][nn], a[mm], bgf[nn]);
                    mma16(au[mm][nn], a[mm], buf[nn]);
                }
        }
        __syncthreads();
    }

    // epilogue: h = half(silu(g)*u*w)
#pragma unroll
    for (int mm = 0; mm < 2; mm++) {
#pragma unroll
        for (int half = 0; half < 2; half++) {
            int rglb = mtile * 128 + warpM + mm * 16 + gl + half * 8;
            bool live = (!ROUTED) || (rglb < Me);
            if (!live) continue;
            float w = 1.0f;
            __half* dst;
            if (ROUTED) {
                int slot = start + rglb;
                w = g_slot_w[slot];
                dst = g_hbuf + (size_t)slot * HDIM + (size_t)ntile * 128;
            } else {
                dst = g_sh + (size_t)rglb * HSDIM + (size_t)ntile * 128;
            }
#pragma unroll
            for (int nn = 0; nn < 4; nn++) {
                int c = warpN + nn * 8 + 2 * kl;
                float gv0 = ag[mm][nn][half * 2], gv1 = ag[mm][nn][half * 2 + 1];
                float uv0 = au[mm][nn][half * 2], uv1 = au[mm][nn][half * 2 + 1];
                __half2 h2 = __floats2half2_rn(silu_f(gv0) * uv0 * w,
                                               silu_f(gv1) * uv1 * w);
                *(__half2*)(dst + c) = h2;
            }
        }
    }
}

// ---------------- down GEMM via mma.sync fp16 ----------------
template <bool ROUTED>
__global__ __launch_bounds__(512, 1)
void down_mma(const __half* __restrict__ Wd, float* __restrict__ Out) {
    extern __shared__ char smem[];
    constexpr int K = ROUTED ? HDIM : HSDIM;
    constexpr int KT = K / 32;
    uint32_t smA = s2u(smem);
    uint32_t smB = smA + 2 * A_ST_BYTES;

    int tid = threadIdx.x, wid = tid >> 5, lane = tid & 31;
    int warpM = (wid >> 2) * 32, warpN = (wid & 3) * 32;
    int gl = lane >> 2, kl = lane & 3;
    int ntile = blockIdx.x, mtile = blockIdx.y;

    int start = 0, Me = T_TOKENS;
    if (ROUTED) {
        int expert = blockIdx.z;
        start = g_offsets[expert];
        Me = g_offsets[expert + 1] - start;
        if (mtile * 128 >= Me) return;
        Wd += (size_t)expert * HDIM * DIM;
    }
    const __half* Abase = (ROUTED ? g_hbuf : g_sh) + (size_t)(start + mtile * 128) * K;

    int arow = tid >> 2, ac = (tid & 3) * 8;
    const __half* pA = Abase + (size_t)arow * K + ac;
    uint32_t dA = smA + (arow * AST + ac) * 2;
    int brw = tid >> 5, bc4 = (tid & 31) * 4;
    const __half* pB = Wd + ((size_t)brw * DIM + (size_t)ntile * 128 + bc4) * 2;
    uint32_t dB = smB + (brw * BSTP + bc4) * 4;

#define DN_COPY(stg, kt) do { \
    cp16(dA + (stg) * A_ST_BYTES, pA + (kt) * 32); \
    cp16(dB + (stg) * B_ST_BYTES, pB + (size_t)(kt) * 16 * DIM * 2); \
    cp_commit(); \
} while (0)

    float acc[2][4][4];
#pragma unroll
    for (int mm = 0; mm < 2; mm++)
#pragma unroll
        for (int nn = 0; nn < 4; nn++)
#pragma unroll
            for (int q = 0; q < 4; q++) acc[mm][nn][q] = 0.f;

    DN_COPY(0, 0);
    for (int kt = 0; kt < KT; kt++) {
        int cur = kt & 1;
        if (kt + 1 < KT) {
            DN_COPY(cur ^ 1, kt + 1);
            asm volatile("cp.async.wait_group 1;" ::: "memory");
        } else {
            asm volatile("cp.async.wait_group 0;" ::: "memory");
        }
        __syncthreads();
        const uint32_t* as = (const uint32_t*)(smem + cur * A_ST_BYTES);
        const uint32_t* bs = (const uint32_t*)(smem + 2 * A_ST_BYTES + cur * B_ST_BYTES);
#pragma unroll
        for (int ks2 = 0; ks2 < 16; ks2 += 8) {
            uint32_t a[2][4];
#pragma unroll
            for (int mm = 0; mm < 2; mm++) {
                int r = warpM + mm * 16 + gl;
                a[mm][0] = as[r * 20 + ks2 + kl];
                a[mm][1] = as[(r + 8) * 20 + ks2 + kl];
                a[mm][2] = as[r * 20 + ks2 + kl + 4];
                a[mm][3] = as[(r + 8) * 20 + ks2 + kl + 4];
            }
            uint32_t bf[4][2];
#pragma unroll
            for (int nn = 0; nn < 4; nn++) {
                int c = warpN + nn * 8 + gl;
                bf[nn][0] = bs[(ks2 + kl) * BSTP + c];
                bf[nn][1] = bs[(ks2 + kl + 4) * BSTP + c];
            }
#pragma unroll
            for (int mm = 0; mm < 2; mm++)
#pragma unroll
                for (int nn = 0; nn < 4; nn++)
                    mma16(acc[mm][nn], a[mm], bf[nn]);
        }
        __syncthreads();
    }

#pragma unroll
    for (int mm = 0; mm < 2; mm++) {
#pragma unroll
        for (int half = 0; half < 2; half++) {
            int rglb = mtile * 128 + warpM + mm * 16 + gl + half * 8;
            bool live = (!ROUTED) || (rglb < Me);
            if (!live) continue;
            float* dst;
            if (ROUTED) {
                int token = g_slot_token[start + rglb];
                dst = Out + (size_t)token * DIM + (size_t)ntile * 128;
            } else {
                dst = Out + (size_t)rglb * DIM + (size_t)ntile * 128;
            }
#pragma unroll
            for (int nn = 0; nn < 4; nn++) {
                int c = warpN + nn * 8 + 2 * kl;
                float v0 = acc[mm][nn][half * 2], v1 = acc[mm][nn][half * 2 + 1];
                if (ROUTED) {
                    atomicAdd(dst + c, v0);
                    atomicAdd(dst + c + 1, v1);
                } else {
                    float2 v; v.x = v0; v.y = v1;
                    *(float2*)(dst + c) = v;
                }
            }
        }
    }
}

// ---------------- launch ----------------
extern "C" void kernel_launch(void* const* d_in, const int* in_sizes, int n_in,
                              void* d_out, int out_size) {
    const float* x   = (const float*)d_in[0];
    const float* rw  = (const float*)d_in[1];
    const float* wg  = (const float*)d_in[2];
    const float* wu  = (const float*)d_in[3];
    const float* wd  = (const float*)d_in[4];
    const float* swg = (const float*)d_in[5];
    const float* swu = (const float*)d_in[6];
    const float* swd = (const float*)d_in[7];
    float* out = (float*)d_out;

    cudaFuncSetAttribute(gateup_mma<false>, cudaFuncAttributeMaxDynamicSharedMemorySize, GU_SMEM);
    cudaFuncSetAttribute(gateup_mma<true>,  cudaFuncAttributeMaxDynamicSharedMemorySize, GU_SMEM);
    cudaFuncSetAttribute(down_mma<false>,   cudaFuncAttributeMaxDynamicSharedMemorySize, DN_SMEM);
    cudaFuncSetAttribute(down_mma<true>,    cudaFuncAttributeMaxDynamicSharedMemorySize, DN_SMEM);

    __half *wgh, *wuh, *wdh, *swgh, *swuh, *swdh;
    cudaGetSymbolAddress((void**)&wgh, g_wgh);
    cudaGetSymbolAddress((void**)&wuh, g_wuh);
    cudaGetSymbolAddress((void**)&wdh, g_wdh);
    cudaGetSymbolAddress((void**)&swgh, g_swgh);
    cudaGetSymbolAddress((void**)&swuh, g_swuh);
    cudaGetSymbolAddress((void**)&swdh, g_swdh);

    zero_small_kernel<<<1, 32>>>();
    router_kernel<<<T_TOKENS / 8, 256>>>(x, rw);
    scan_kernel<<<1, 32>>>();
    scatter_kernel<<<NSLOTS / 256, 256>>>();
    gather_half_kernel<<<NSLOTS + PAD + T_TOKENS, 256>>>(x);

    // weight conversions (fp32 -> fp16 k-pair interleaved)
    convw_kernel<<<(NEXP * DIM / 2) * (HDIM / 4) / 256, 256>>>(wg, wgh, NEXP * DIM, HDIM);
    convw_kernel<<<(NEXP * DIM / 2) * (HDIM / 4) / 256, 256>>>(wu, wuh, NEXP * DIM, HDIM);
    convw_kernel<<<(NEXP * HDIM / 2) * (DIM / 4) / 256, 256>>>(wd, wdh, NEXP * HDIM, DIM);
    convw_kernel<<<(DIM / 2) * (HSDIM / 4) / 256, 256>>>(swg, swgh, DIM, HSDIM);
    convw_kernel<<<(DIM / 2) * (HSDIM / 4) / 256, 256>>>(swu, swuh, DIM, HSDIM);
    convw_kernel<<<(HSDIM / 2) * (DIM / 4) / 256, 256>>>(swd, swdh, HSDIM, DIM);

    // shared expert
    gateup_mma<false><<<dim3(HSDIM / 128, T_TOKENS / 128, 1), 512, GU_SMEM>>>(swgh, swuh);
    down_mma<false><<<dim3(DIM / 128, T_TOKENS / 128, 1), 512, DN_SMEM>>>(swdh, out);
    // routed experts
    gateup_mma<true><<<dim3(HDIM / 128, NSLOTS / 128, NEXP), 512, GU_SMEM>>>(wgh, wuh);
    down_mma<true><<<dim3(DIM / 128, NSLOTS / 128, NEXP), 512, DN_SMEM>>>(wdh, out);
}

// round 11
// speedup vs baseline: 5.6629x; 1.1324x over previous
#include <cuda_runtime.h>
#include <cuda_fp16.h>
#include <cstdint>

#define T_TOKENS 4096
#define DIM      2048
#define NEXP     8
#define HDIM     1024
#define HSDIM    2048
#define NSLOTS   8192
#define PAD      128

// ---------------- scratch (device globals; no allocation allowed) ----------------
__device__ __half g_xg[(size_t)(NSLOTS + PAD) * DIM];    // gathered fp16 x by slot
__device__ __half g_xr[(size_t)T_TOKENS * DIM];          // fp16 dense x
__device__ __half g_hbuf[(size_t)(NSLOTS + PAD) * HDIM]; // routed h (weight-folded)
__device__ __half g_sh[(size_t)T_TOKENS * HSDIM];        // shared-expert h
__device__ __half g_wgh[(size_t)NEXP * DIM * HDIM];      // transposed [e][n=h][k=d] fp16
__device__ __half g_wuh[(size_t)NEXP * DIM * HDIM];
__device__ __half g_wdh[(size_t)NEXP * HDIM * DIM];      // [e][n=d][k=h]
__device__ __half g_swgh[(size_t)DIM * HSDIM];           // [n=hs][k=d]
__device__ __half g_swuh[(size_t)DIM * HSDIM];
__device__ __half g_swdh[(size_t)HSDIM * DIM];           // [n=d][k=hs]
__device__ int   g_slot_token[NSLOTS];
__device__ float g_slot_w[NSLOTS];
__device__ int   g_counts[NEXP];
__device__ int   g_fill[NEXP];
__device__ int   g_offsets[NEXP + 1];
__device__ int   g_eidx[NSLOTS];
__device__ float g_topw[NSLOTS];

// ---------------- helpers ----------------
__device__ __forceinline__ float silu_f(float g) {
    return g * (1.0f / (1.0f + __expf(-g)));
}
__device__ __forceinline__ uint32_t s2u(const void* p) {
    uint32_t a;
    asm("{ .reg .u64 t; cvta.to.shared.u64 t, %1; cvt.u32.u64 %0, t; }" : "=r"(a) : "l"(p));
    return a;
}
__device__ __forceinline__ void cp16(uint32_t s, const void* g) {
    asm volatile("cp.async.cg.shared.global [%0], [%1], 16;" :: "r"(s), "l"(g));
}
__device__ __forceinline__ void cp_commit() {
    asm volatile("cp.async.commit_group;" ::: "memory");
}
__device__ __forceinline__ void mma16(float* c, const uint32_t* a, const uint32_t* b) {
    asm volatile("mma.sync.aligned.m16n8k16.row.col.f32.f16.f16.f32 "
        "{%0,%1,%2,%3}, {%4,%5,%6,%7}, {%8,%9}, {%0,%1,%2,%3};"
        : "+f"(c[0]), "+f"(c[1]), "+f"(c[2]), "+f"(c[3])
        : "r"(a[0]), "r"(a[1]), "r"(a[2]), "r"(a[3]), "r"(b[0]), "r"(b[1]));
}
__device__ __forceinline__ void ldsm4(uint32_t* d, uint32_t addr) {
    asm volatile("ldmatrix.sync.aligned.m8n8.x4.shared.b16 {%0,%1,%2,%3}, [%4];"
        : "=r"(d[0]), "=r"(d[1]), "=r"(d[2]), "=r"(d[3]) : "r"(addr));
}

// SMEM geometry: every tile (A or B) = 128 rows x 40 halves (32 data + 8 pad)
#define AST 40
#define TILE_B 10240                       // bytes per tile
#define GU_SMEM (3 * 3 * TILE_B)           // 92160 (3 stages x {A,Bg,Bu})
#define DN_SMEM (3 * 2 * TILE_B)           // 61440 (3 stages x {A,B})

// ---------------- routing kernels ----------------
__global__ void zero_small_kernel() {
    int i = threadIdx.x;
    if (i < NEXP) { g_counts[i] = 0; g_fill[i] = 0; }
}

__global__ void router_kernel(const float* __restrict__ x, const float* __restrict__ rw) {
    int t = (blockIdx.x * blockDim.x + threadIdx.x) >> 5;
    int lane = threadIdx.x & 31;
    if (t >= T_TOKENS) return;
    const float* xr = x + (size_t)t * DIM;
    float lg[NEXP];
#pragma unroll
    for (int e = 0; e < NEXP; e++) lg[e] = 0.f;
    for (int d = lane; d < DIM; d += 32) {
        float xv = xr[d];
        const float* r = rw + (size_t)d * NEXP;
#pragma unroll
        for (int e = 0; e < NEXP; e++) lg[e] += xv * r[e];
    }
#pragma unroll
    for (int e = 0; e < NEXP; e++) {
#pragma unroll
        for (int o = 16; o; o >>= 1) lg[e] += __shfl_xor_sync(0xffffffffu, lg[e], o);
    }
    if (lane == 0) {
        float mx = lg[0];
#pragma unroll
        for (int e = 1; e < NEXP; e++) mx = fmaxf(mx, lg[e]);
        float p[NEXP];
#pragma unroll
        for (int e = 0; e < NEXP; e++) p[e] = __expf(lg[e] - mx);
        int i1 = 0;
#pragma unroll
        for (int e = 1; e < NEXP; e++) if (p[e] > p[i1]) i1 = e;
        int i2 = (i1 == 0) ? 1 : 0;
#pragma unroll
        for (int e = 0; e < NEXP; e++) if (e != i1 && p[e] > p[i2]) i2 = e;
        float w1 = p[i1], w2 = p[i2];
        float s = w1 + w2;
        w1 /= s; w2 /= s;
        g_eidx[2 * t] = i1; g_eidx[2 * t + 1] = i2;
        g_topw[2 * t] = w1; g_topw[2 * t + 1] = w2;
        atomicAdd(&g_counts[i1], 1);
        atomicAdd(&g_counts[i2], 1);
    }
}

__global__ void scan_kernel() {
    if (threadIdx.x == 0) {
        int acc = 0;
        for (int e = 0; e < NEXP; e++) { g_offsets[e] = acc; acc += g_counts[e]; }
        g_offsets[NEXP] = acc;
    }
}

__global__ void scatter_kernel() {
    int i = blockIdx.x * blockDim.x + threadIdx.x;
    if (i >= NSLOTS) return;
    int e = g_eidx[i];
    int pos = g_offsets[e] + atomicAdd(&g_fill[e], 1);
    g_slot_token[pos] = i >> 1;
    g_slot_w[pos] = g_topw[i];
}

// ---------------- weight fp32 [K][N] -> fp16 transposed [N][K] ----------------
__global__ void convw_t_kernel(const float* __restrict__ src, __half* __restrict__ dst,
                               int K, int N) {
    __shared__ float t[32][33];
    size_t boff = (size_t)blockIdx.z * K * N;
    const float* ip = src + boff;
    __half* op = dst + boff;
    int c0 = blockIdx.x * 32;  // N dim
    int r0 = blockIdx.y * 32;  // K dim
    int x = threadIdx.x, y = threadIdx.y;
#pragma unroll
    for (int i = 0; i < 32; i += 8)
        t[y + i][x] = ip[(size_t)(r0 + y + i) * N + (c0 + x)];
    __syncthreads();
    int tid = y * 32 + x;
#pragma unroll
    for (int q = 0; q < 2; q++) {
        int p = tid * 2 + q;
        int nl = p >> 4, kc = p & 15;
        __half2 h2 = __floats2half2_rn(t[2 * kc][nl], t[2 * kc + 1][nl]);
        *(__half2*)(op + (size_t)(c0 + nl) * K + r0 + 2 * kc) = h2;
    }
}

// gather x rows into slot order (fp16, +zero pad) and dense fp16 copy
__global__ void gather_half_kernel(const float* __restrict__ x) {
    int row = blockIdx.x;
    int c0 = threadIdx.x * 8;
    __half h[8];
    if (row < NSLOTS + PAD) {
        __half* dst = g_xg + (size_t)row * DIM;
        if (row < NSLOTS) {
            const float* src = x + (size_t)g_slot_token[row] * DIM;
            float4 v0 = *(const float4*)(src + c0);
            float4 v1 = *(const float4*)(src + c0 + 4);
            h[0] = __float2half(v0.x); h[1] = __float2half(v0.y);
            h[2] = __float2half(v0.z); h[3] = __float2half(v0.w);
            h[4] = __float2half(v1.x); h[5] = __float2half(v1.y);
            h[6] = __float2half(v1.z); h[7] = __float2half(v1.w);
        } else {
#pragma unroll
            for (int q = 0; q < 8; q++) h[q] = __float2half(0.f);
        }
        *(uint4*)(dst + c0) = *(uint4*)h;
    } else {
        int r = row - (NSLOTS + PAD);
        const float* src = x + (size_t)r * DIM;
        float4 v0 = *(const float4*)(src + c0);
        float4 v1 = *(const float4*)(src + c0 + 4);
        h[0] = __float2half(v0.x); h[1] = __float2half(v0.y);
        h[2] = __float2half(v0.z); h[3] = __float2half(v0.w);
        h[4] = __float2half(v1.x); h[5] = __float2half(v1.y);
        h[6] = __float2half(v1.z); h[7] = __float2half(v1.w);
        *(uint4*)(g_xr + (size_t)r * DIM + c0) = *(uint4*)h;
    }
}

// ---------------- fused gate/up GEMM: mma.sync fp16 + ldmatrix, 3-stage ----------------
// Block 128x128, BK=32, 512 threads (16 warps 4x4), warp tile 32x32.
template <bool ROUTED>
__global__ __launch_bounds__(512, 1)
void gateup_mma(const __half* __restrict__ Wg, const __half* __restrict__ Wu) {
    extern __shared__ char smem[];
    constexpr int KT = DIM / 32;  // 64
    uint32_t smA = s2u(smem);

    int tid = threadIdx.x, wid = tid >> 5, lane = tid & 31;
    int warpM = (wid >> 2) * 32, warpN = (wid & 3) * 32;
    int gl = lane >> 2, kl = lane & 3;
    int ntile = blockIdx.x, mtile = blockIdx.y;

    int start = 0, Me = T_TOKENS;
    if (ROUTED) {
        int expert = blockIdx.z;
        start = g_offsets[expert];
        Me = g_offsets[expert + 1] - start;
        if (mtile * 128 >= Me) return;
        Wg += (size_t)expert * DIM * HDIM;
        Wu += (size_t)expert * DIM * HDIM;
    }
    const __half* Abase = (ROUTED ? g_xg : g_xr) + (size_t)(start + mtile * 128) * DIM;

    // cp.async lanes: row = tid/4 (0..127), seg = tid%4 (16B each)
    int crow = tid >> 2, seg = tid & 3;
    const __half* pA = Abase + (size_t)crow * DIM + seg * 8;
    const __half* pG = Wg + (size_t)(ntile * 128 + crow) * DIM + seg * 8;
    const __half* pU = Wu + (size_t)(ntile * 128 + crow) * DIM + seg * 8;
    uint32_t dOff = smA + (crow * AST + seg * 8) * 2;

#define GU_COPY(stg, kt) do { \
    uint32_t _b = dOff + (stg) * (3 * TILE_B); \
    cp16(_b,              pA + (kt) * 32); \
    cp16(_b + TILE_B,     pG + (kt) * 32); \
    cp16(_b + 2 * TILE_B, pU + (kt) * 32); \
    cp_commit(); \
} while (0)

    // ldmatrix lane offsets (bytes within a tile)
    int l8 = lane & 7, lj = lane >> 3;
    uint32_t offA = (uint32_t)((warpM + (lj & 1) * 8 + l8) * AST + (lj >> 1) * 8) * 2;
    uint32_t offB = (uint32_t)((warpN + (lj >> 1) * 8 + l8) * AST + (lj & 1) * 8) * 2;

    float ag[2][4][4], au[2][4][4];
#pragma unroll
    for (int mm = 0; mm < 2; mm++)
#pragma unroll
        for (int nn = 0; nn < 4; nn++)
#pragma unroll
            for (int q = 0; q < 4; q++) { ag[mm][nn][q] = 0.f; au[mm][nn][q] = 0.f; }

    GU_COPY(0, 0);
    GU_COPY(1, 1);
    for (int kt = 0; kt < KT; kt++) {
        int cur = kt % 3;
        // wait for this tile's copies (own), then barrier => all threads' copies visible
        if (kt + 1 < KT) asm volatile("cp.async.wait_group 1;" ::: "memory");
        else             asm volatile("cp.async.wait_group 0;" ::: "memory");
        __syncthreads();
        // issue prefetch AFTER barrier: target buffer's last readers are done
        if (kt + 2 < KT) GU_COPY((kt + 2) % 3, kt + 2);
        uint32_t base = smA + cur * (3 * TILE_B);
#pragma unroll
        for (int ks = 0; ks < 2; ks++) {
            uint32_t a0[4], a1[4], bg0[4], bg1[4], bu0[4], bu1[4];
            ldsm4(a0, base + offA + ks * 32);
            ldsm4(a1, base + offA + 1280 + ks * 32);
            ldsm4(bg0, base + TILE_B + offB + ks * 32);
            ldsm4(bg1, base + TILE_B + offB + 1280 + ks * 32);
            ldsm4(bu0, base + 2 * TILE_B + offB + ks * 32);
            ldsm4(bu1, base + 2 * TILE_B + offB + 1280 + ks * 32);
#pragma unroll
            for (int mm = 0; mm < 2; mm++) {
                const uint32_t* a = mm ? a1 : a0;
                mma16(ag[mm][0], a, bg0);
                mma16(ag[mm][1], a, bg0 + 2);
                mma16(ag[mm][2], a, bg1);
                mma16(ag[mm][3], a, bg1 + 2);
                mma16(au[mm][0], a, bu0);
                mma16(au[mm][1], a, bu0 + 2);
                mma16(au[mm][2], a, bu1);
                mma16(au[mm][3], a, bu1 + 2);
            }
        }
    }

    // epilogue: h = half(silu(g)*u*w)
#pragma unroll
    for (int mm = 0; mm < 2; mm++) {
#pragma unroll
        for (int hh = 0; hh < 2; hh++) {
            int rglb = mtile * 128 + warpM + mm * 16 + gl + hh * 8;
            bool live = (!ROUTED) || (rglb < Me);
            if (!live) continue;
            float w = 1.0f;
            __half* dst;
            if (ROUTED) {
                int slot = start + rglb;
                w = g_slot_w[slot];
                dst = g_hbuf + (size_t)slot * HDIM + (size_t)ntile * 128;
            } else {
                dst = g_sh + (size_t)rglb * HSDIM + (size_t)ntile * 128;
            }
#pragma unroll
            for (int nn = 0; nn < 4; nn++) {
                int c = warpN + nn * 8 + 2 * kl;
                float gv0 = ag[mm][nn][hh * 2], gv1 = ag[mm][nn][hh * 2 + 1];
                float uv0 = au[mm][nn][hh * 2], uv1 = au[mm][nn][hh * 2 + 1];
                __half2 h2 = __floats2half2_rn(silu_f(gv0) * uv0 * w,
                                               silu_f(gv1) * uv1 * w);
                *(__half2*)(dst + c) = h2;
            }
        }
    }
}

// ---------------- down GEMM: mma.sync fp16 + ldmatrix, 3-stage ----------------
template <bool ROUTED>
__global__ __launch_bounds__(512, 1)
void down_mma(const __half* __restrict__ Wd, float* __restrict__ Out) {
    extern __shared__ char smem[];
    constexpr int K = ROUTED ? HDIM : HSDIM;
    constexpr int KT = K / 32;
    uint32_t smA = s2u(smem);

    int tid = threadIdx.x, wid = tid >> 5, lane = tid & 31;
    int warpM = (wid >> 2) * 32, warpN = (wid & 3) * 32;
    int gl = lane >> 2, kl = lane & 3;
    int ntile = blockIdx.x, mtile = blockIdx.y;

    int start = 0, Me = T_TOKENS;
    if (ROUTED) {
        int expert = blockIdx.z;
        start = g_offsets[expert];
        Me = g_offsets[expert + 1] - start;
        if (mtile * 128 >= Me) return;
        Wd += (size_t)expert * HDIM * DIM;
    }
    const __half* Abase = (ROUTED ? g_hbuf : g_sh) + (size_t)(start + mtile * 128) * K;

    int crow = tid >> 2, seg = tid & 3;
    const __half* pA = Abase + (size_t)crow * K + seg * 8;
    const __half* pB = Wd + (size_t)(ntile * 128 + crow) * K + seg * 8;
    uint32_t dOff = smA + (crow * AST + seg * 8) * 2;

#define DN_COPY(stg, kt) do { \
    uint32_t _b = dOff + (stg) * (2 * TILE_B); \
    cp16(_b,          pA + (kt) * 32); \
    cp16(_b + TILE_B, pB + (kt) * 32); \
    cp_commit(); \
} while (0)

    int l8 = lane & 7, lj = lane >> 3;
    uint32_t offA = (uint32_t)((warpM + (lj & 1) * 8 + l8) * AST + (lj >> 1) * 8) * 2;
    uint32_t offB = (uint32_t)((warpN + (lj >> 1) * 8 + l8) * AST + (lj & 1) * 8) * 2;

    float acc[2][4][4];
#pragma unroll
    for (int mm = 0; mm < 2; mm++)
#pragma unroll
        for (int nn = 0; nn < 4; nn++)
#pragma unroll
            for (int q = 0; q < 4; q++) acc[mm][nn][q] = 0.f;

    DN_COPY(0, 0);
    DN_COPY(1, 1);
    for (int kt = 0; kt < KT; kt++) {
        int cur = kt % 3;
        if (kt + 1 < KT) asm volatile("cp.async.wait_group 1;" ::: "memory");
        else             asm volatile("cp.async.wait_group 0;" ::: "memory");
        __syncthreads();
        if (kt + 2 < KT) DN_COPY((kt + 2) % 3, kt + 2);
        uint32_t base = smA + cur * (2 * TILE_B);
#pragma unroll
        for (int ks = 0; ks < 2; ks++) {
            uint32_t a0[4], a1[4], b0[4], b1[4];
            ldsm4(a0, base + offA + ks * 32);
            ldsm4(a1, base + offA + 1280 + ks * 32);
            ldsm4(b0, base + TILE_B + offB + ks * 32);
            ldsm4(b1, base + TILE_B + offB + 1280 + ks * 32);
#pragma unroll
            for (int mm = 0; mm < 2; mm++) {
                const uint32_t* a = mm ? a1 : a0;
                mma16(acc[mm][0], a, b0);
                mma16(acc[mm][1], a, b0 + 2);
                mma16(acc[mm][2], a, b1);
                mma16(acc[mm][3], a, b1 + 2);
            }
        }
    }

#pragma unroll
    for (int mm = 0; mm < 2; mm++) {
#pragma unroll
        for (int hh = 0; hh < 2; hh++) {
            int rglb = mtile * 128 + warpM + mm * 16 + gl + hh * 8;
            bool live = (!ROUTED) || (rglb < Me);
            if (!live) continue;
            float* dst;
            if (ROUTED) {
                int token = g_slot_token[start + rglb];
                dst = Out + (size_t)token * DIM + (size_t)ntile * 128;
            } else {
                dst = Out + (size_t)rglb * DIM + (size_t)ntile * 128;
            }
#pragma unroll
            for (int nn = 0; nn < 4; nn++) {
                int c = warpN + nn * 8 + 2 * kl;
                float v0 = acc[mm][nn][hh * 2], v1 = acc[mm][nn][hh * 2 + 1];
                if (ROUTED) {
                    atomicAdd(dst + c, v0);
                    atomicAdd(dst + c + 1, v1);
                } else {
                    float2 v; v.x = v0; v.y = v1;
                    *(float2*)(dst + c) = v;
                }
            }
        }
    }
}

// ---------------- launch ----------------
extern "C" void kernel_launch(void* const* d_in, const int* in_sizes, int n_in,
                              void* d_out, int out_size) {
    const float* x   = (const float*)d_in[0];
    const float* rw  = (const float*)d_in[1];
    const float* wg  = (const float*)d_in[2];
    const float* wu  = (const float*)d_in[3];
    const float* wd  = (const float*)d_in[4];
    const float* swg = (const float*)d_in[5];
    const float* swu = (const float*)d_in[6];
    const float* swd = (const float*)d_in[7];
    float* out = (float*)d_out;

    cudaFuncSetAttribute(gateup_mma<false>, cudaFuncAttributeMaxDynamicSharedMemorySize, GU_SMEM);
    cudaFuncSetAttribute(gateup_mma<true>,  cudaFuncAttributeMaxDynamicSharedMemorySize, GU_SMEM);
    cudaFuncSetAttribute(down_mma<false>,   cudaFuncAttributeMaxDynamicSharedMemorySize, DN_SMEM);
    cudaFuncSetAttribute(down_mma<true>,    cudaFuncAttributeMaxDynamicSharedMemorySize, DN_SMEM);

    __half *wgh, *wuh, *wdh, *swgh, *swuh, *swdh;
    cudaGetSymbolAddress((void**)&wgh, g_wgh);
    cudaGetSymbolAddress((void**)&wuh, g_wuh);
    cudaGetSymbolAddress((void**)&wdh, g_wdh);
    cudaGetSymbolAddress((void**)&swgh, g_swgh);
    cudaGetSymbolAddress((void**)&swuh, g_swuh);
    cudaGetSymbolAddress((void**)&swdh, g_swdh);

    zero_small_kernel<<<1, 32>>>();
    router_kernel<<<T_TOKENS / 8, 256>>>(x, rw);
    scan_kernel<<<1, 32>>>();
    scatter_kernel<<<NSLOTS / 256, 256>>>();
    gather_half_kernel<<<NSLOTS + PAD + T_TOKENS, 256>>>(x);

    // weight conversions: fp32 [K][N] -> fp16 [N][K]
    convw_t_kernel<<<dim3(HDIM / 32, DIM / 32, NEXP), dim3(32, 8)>>>(wg, wgh, DIM, HDIM);
    convw_t_kernel<<<dim3(HDIM / 32, DIM / 32, NEXP), dim3(32, 8)>>>(wu, wuh, DIM, HDIM);
    convw_t_kernel<<<dim3(DIM / 32, HDIM / 32, NEXP), dim3(32, 8)>>>(wd, wdh, HDIM, DIM);
    convw_t_kernel<<<dim3(HSDIM / 32, DIM / 32, 1), dim3(32, 8)>>>(swg, swgh, DIM, HSDIM);
    convw_t_kernel<<<dim3(HSDIM / 32, DIM / 32, 1), dim3(32, 8)>>>(swu, swuh, DIM, HSDIM);
    convw_t_kernel<<<dim3(DIM / 32, HSDIM / 32, 1), dim3(32, 8)>>>(swd, swdh, HSDIM, DIM);

    // shared expert
    gateup_mma<false><<<dim3(HSDIM / 128, T_TOKENS / 128, 1), 512, GU_SMEM>>>(swgh, swuh);
    down_mma<false><<<dim3(DIM / 128, T_TOKENS / 128, 1), 512, DN_SMEM>>>(swdh, out);
    // routed experts
    gateup_mma<true><<<dim3(HDIM / 128, NSLOTS / 128, NEXP), 512, GU_SMEM>>>(wgh, wuh);
    down_mma<true><<<dim3(DIM / 128, NSLOTS / 128, NEXP), 512, DN_SMEM>>>(wdh, out);
}

// round 12
// speedup vs baseline: 5.8099x; 1.0259x over previous
#include <cuda_runtime.h>
#include <cuda_fp16.h>
#include <cstdint>

#define T_TOKENS 4096
#define DIM      2048
#define NEXP     8
#define HDIM     1024
#define HSDIM    2048
#define NSLOTS   8192
#define PAD      128

// ---------------- scratch (device globals; no allocation allowed) ----------------
__device__ __half g_xr[(size_t)T_TOKENS * DIM];          // fp16 dense x
__device__ __half g_hbuf[(size_t)(NSLOTS + PAD) * HDIM]; // routed h (weight-folded)
__device__ __half g_sh[(size_t)T_TOKENS * HSDIM];        // shared-expert h
__device__ __half g_wgh[(size_t)NEXP * DIM * HDIM];      // transposed [e][n=h][k=d] fp16
__device__ __half g_wuh[(size_t)NEXP * DIM * HDIM];
__device__ __half g_wdh[(size_t)NEXP * HDIM * DIM];      // [e][n=d][k=h]
__device__ __half g_swgh[(size_t)DIM * HSDIM];           // [n=hs][k=d]
__device__ __half g_swuh[(size_t)DIM * HSDIM];
__device__ __half g_swdh[(size_t)HSDIM * DIM];           // [n=d][k=hs]
__device__ int   g_slot_token[NSLOTS];
__device__ float g_slot_w[NSLOTS];
__device__ int   g_counts[NEXP];
__device__ int   g_fill[NEXP];
__device__ int   g_offsets[NEXP + 1];
__device__ int   g_eidx[NSLOTS];
__device__ float g_topw[NSLOTS];

// ---------------- helpers ----------------
__device__ __forceinline__ float silu_f(float g) {
    return g * (1.0f / (1.0f + __expf(-g)));
}
__device__ __forceinline__ uint32_t s2u(const void* p) {
    uint32_t a;
    asm("{ .reg .u64 t; cvta.to.shared.u64 t, %1; cvt.u32.u64 %0, t; }" : "=r"(a) : "l"(p));
    return a;
}
__device__ __forceinline__ void cp16(uint32_t s, const void* g) {
    asm volatile("cp.async.cg.shared.global [%0], [%1], 16;" :: "r"(s), "l"(g));
}
__device__ __forceinline__ void cp_commit() {
    asm volatile("cp.async.commit_group;" ::: "memory");
}
__device__ __forceinline__ void mma16(float* c, const uint32_t* a, const uint32_t* b) {
    asm volatile("mma.sync.aligned.m16n8k16.row.col.f32.f16.f16.f32 "
        "{%0,%1,%2,%3}, {%4,%5,%6,%7}, {%8,%9}, {%0,%1,%2,%3};"
        : "+f"(c[0]), "+f"(c[1]), "+f"(c[2]), "+f"(c[3])
        : "r"(a[0]), "r"(a[1]), "r"(a[2]), "r"(a[3]), "r"(b[0]), "r"(b[1]));
}
__device__ __forceinline__ void ldsm4(uint32_t* d, uint32_t addr) {
    asm volatile("ldmatrix.sync.aligned.m8n8.x4.shared.b16 {%0,%1,%2,%3}, [%4];"
        : "=r"(d[0]), "=r"(d[1]), "=r"(d[2]), "=r"(d[3]) : "r"(addr));
}

// SMEM geometry: every tile (A or B) = 128 rows x 40 halves (32 data + 8 pad)
#define AST 40
#define TILE_B 10240                       // bytes per tile
#define GU_SMEM (3 * 3 * TILE_B)           // 92160 (3 stages x {A,Bg,Bu})
#define DN_SMEM (3 * 2 * TILE_B)           // 61440 (3 stages x {A,B})

// ---------------- routing kernels ----------------
__global__ void zero_small_kernel() {
    int i = threadIdx.x;
    if (i < NEXP) { g_counts[i] = 0; g_fill[i] = 0; }
}

__global__ void router_kernel(const float* __restrict__ x, const float* __restrict__ rw) {
    int t = (blockIdx.x * blockDim.x + threadIdx.x) >> 5;
    int lane = threadIdx.x & 31;
    if (t >= T_TOKENS) return;
    const float* xr = x + (size_t)t * DIM;
    float lg[NEXP];
#pragma unroll
    for (int e = 0; e < NEXP; e++) lg[e] = 0.f;
    for (int d = lane; d < DIM; d += 32) {
        float xv = xr[d];
        const float* r = rw + (size_t)d * NEXP;
#pragma unroll
        for (int e = 0; e < NEXP; e++) lg[e] += xv * r[e];
    }
#pragma unroll
    for (int e = 0; e < NEXP; e++) {
#pragma unroll
        for (int o = 16; o; o >>= 1) lg[e] += __shfl_xor_sync(0xffffffffu, lg[e], o);
    }
    if (lane == 0) {
        float mx = lg[0];
#pragma unroll
        for (int e = 1; e < NEXP; e++) mx = fmaxf(mx, lg[e]);
        float p[NEXP];
#pragma unroll
        for (int e = 0; e < NEXP; e++) p[e] = __expf(lg[e] - mx);
        int i1 = 0;
#pragma unroll
        for (int e = 1; e < NEXP; e++) if (p[e] > p[i1]) i1 = e;
        int i2 = (i1 == 0) ? 1 : 0;
#pragma unroll
        for (int e = 0; e < NEXP; e++) if (e != i1 && p[e] > p[i2]) i2 = e;
        float w1 = p[i1], w2 = p[i2];
        float s = w1 + w2;
        w1 /= s; w2 /= s;
        g_eidx[2 * t] = i1; g_eidx[2 * t + 1] = i2;
        g_topw[2 * t] = w1; g_topw[2 * t + 1] = w2;
        atomicAdd(&g_counts[i1], 1);
        atomicAdd(&g_counts[i2], 1);
    }
}

__global__ void scan_kernel() {
    if (threadIdx.x == 0) {
        int acc = 0;
        for (int e = 0; e < NEXP; e++) { g_offsets[e] = acc; acc += g_counts[e]; }
        g_offsets[NEXP] = acc;
    }
}

__global__ void scatter_kernel() {
    int i = blockIdx.x * blockDim.x + threadIdx.x;
    if (i >= NSLOTS) return;
    int e = g_eidx[i];
    int pos = g_offsets[e] + atomicAdd(&g_fill[e], 1);
    g_slot_token[pos] = i >> 1;
    g_slot_w[pos] = g_topw[i];
}

// ---------------- weight fp32 [K][N] -> fp16 transposed [N][K] ----------------
__global__ void convw_t_kernel(const float* __restrict__ src, __half* __restrict__ dst,
                               int K, int N) {
    __shared__ float t[32][33];
    size_t boff = (size_t)blockIdx.z * K * N;
    const float* ip = src + boff;
    __half* op = dst + boff;
    int c0 = blockIdx.x * 32;  // N dim
    int r0 = blockIdx.y * 32;  // K dim
    int x = threadIdx.x, y = threadIdx.y;
#pragma unroll
    for (int i = 0; i < 32; i += 8)
        t[y + i][x] = ip[(size_t)(r0 + y + i) * N + (c0 + x)];
    __syncthreads();
    int tid = y * 32 + x;
#pragma unroll
    for (int q = 0; q < 2; q++) {
        int p = tid * 2 + q;
        int nl = p >> 4, kc = p & 15;
        __half2 h2 = __floats2half2_rn(t[2 * kc][nl], t[2 * kc + 1][nl]);
        *(__half2*)(op + (size_t)(c0 + nl) * K + r0 + 2 * kc) = h2;
    }
}

// dense fp32 -> fp16 activation conversion
__global__ void conv_x_kernel(const float* __restrict__ x) {
    int r = blockIdx.x;
    int c0 = threadIdx.x * 8;
    const float* src = x + (size_t)r * DIM;
    float4 v0 = *(const float4*)(src + c0);
    float4 v1 = *(const float4*)(src + c0 + 4);
    __half h[8];
    h[0] = __float2half(v0.x); h[1] = __float2half(v0.y);
    h[2] = __float2half(v0.z); h[3] = __float2half(v0.w);
    h[4] = __float2half(v1.x); h[5] = __float2half(v1.y);
    h[6] = __float2half(v1.z); h[7] = __float2half(v1.w);
    *(uint4*)(g_xr + (size_t)r * DIM + c0) = *(uint4*)h;
}

// ---------------- fused gate/up GEMM: mma.sync fp16 + ldmatrix, 3-stage ----------------
// Block 128x128, BK=32, 512 threads (16 warps 4x4), warp tile 32x32.
// ROUTED: A rows gathered inline from g_xr via g_slot_token.
template <bool ROUTED>
__global__ __launch_bounds__(512, 1)
void gateup_mma(const __half* __restrict__ Wg, const __half* __restrict__ Wu) {
    extern __shared__ char smem[];
    constexpr int KT = DIM / 32;  // 64
    uint32_t smA = s2u(smem);

    int tid = threadIdx.x, wid = tid >> 5, lane = tid & 31;
    int warpM = (wid >> 2) * 32, warpN = (wid & 3) * 32;
    int gl = lane >> 2, kl = lane & 3;
    int ntile = blockIdx.x, mtile = blockIdx.y;

    int start = 0, Me = T_TOKENS;
    if (ROUTED) {
        int expert = blockIdx.z;
        start = g_offsets[expert];
        Me = g_offsets[expert + 1] - start;
        if (mtile * 128 >= Me) return;
        Wg += (size_t)expert * DIM * HDIM;
        Wu += (size_t)expert * DIM * HDIM;
    }

    // cp.async lanes: row = tid/4 (0..127), seg = tid%4 (16B each)
    int crow = tid >> 2, seg = tid & 3;
    const __half* pA;
    if (ROUTED) {
        int rr = mtile * 128 + crow;
        if (rr >= Me) rr = Me - 1;                     // clamp; epilogue masks
        pA = g_xr + (size_t)g_slot_token[start + rr] * DIM + seg * 8;
    } else {
        pA = g_xr + (size_t)(mtile * 128 + crow) * DIM + seg * 8;
    }
    const __half* pG = Wg + (size_t)(ntile * 128 + crow) * DIM + seg * 8;
    const __half* pU = Wu + (size_t)(ntile * 128 + crow) * DIM + seg * 8;
    uint32_t dOff = smA + (crow * AST + seg * 8) * 2;

#define GU_COPY(stg, kt) do { \
    uint32_t _b = dOff + (stg) * (3 * TILE_B); \
    cp16(_b,              pA + (kt) * 32); \
    cp16(_b + TILE_B,     pG + (kt) * 32); \
    cp16(_b + 2 * TILE_B, pU + (kt) * 32); \
    cp_commit(); \
} while (0)

    // ldmatrix lane offsets (bytes within a tile)
    int l8 = lane & 7, lj = lane >> 3;
    uint32_t offA = (uint32_t)((warpM + (lj & 1) * 8 + l8) * AST + (lj >> 1) * 8) * 2;
    uint32_t offB = (uint32_t)((warpN + (lj >> 1) * 8 + l8) * AST + (lj & 1) * 8) * 2;

    float ag[2][4][4], au[2][4][4];
#pragma unroll
    for (int mm = 0; mm < 2; mm++)
#pragma unroll
        for (int nn = 0; nn < 4; nn++)
#pragma unroll
            for (int q = 0; q < 4; q++) { ag[mm][nn][q] = 0.f; au[mm][nn][q] = 0.f; }

    GU_COPY(0, 0);
    GU_COPY(1, 1);
    for (int kt = 0; kt < KT; kt++) {
        int cur = kt % 3;
        // wait for this tile's copies (own), then barrier => all threads' copies visible
        if (kt + 1 < KT) asm volatile("cp.async.wait_group 1;" ::: "memory");
        else             asm volatile("cp.async.wait_group 0;" ::: "memory");
        __syncthreads();
        // issue prefetch AFTER barrier: target buffer's last readers are done
        if (kt + 2 < KT) GU_COPY((kt + 2) % 3, kt + 2);
        uint32_t base = smA + cur * (3 * TILE_B);
#pragma unroll
        for (int ks = 0; ks < 2; ks++) {
            uint32_t a0[4], a1[4], bg0[4], bg1[4], bu0[4], bu1[4];
            ldsm4(a0, base + offA + ks * 32);
            ldsm4(a1, base + offA + 1280 + ks * 32);
            ldsm4(bg0, base + TILE_B + offB + ks * 32);
            ldsm4(bg1, base + TILE_B + offB + 1280 + ks * 32);
            ldsm4(bu0, base + 2 * TILE_B + offB + ks * 32);
            ldsm4(bu1, base + 2 * TILE_B + offB + 1280 + ks * 32);
#pragma unroll
            for (int mm = 0; mm < 2; mm++) {
                const uint32_t* a = mm ? a1 : a0;
                mma16(ag[mm][0], a, bg0);
                mma16(ag[mm][1], a, bg0 + 2);
                mma16(ag[mm][2], a, bg1);
                mma16(ag[mm][3], a, bg1 + 2);
                mma16(au[mm][0], a, bu0);
                mma16(au[mm][1], a, bu0 + 2);
                mma16(au[mm][2], a, bu1);
                mma16(au[mm][3], a, bu1 + 2);
            }
        }
    }

    // epilogue: h = half(silu(g)*u*w)
#pragma unroll
    for (int mm = 0; mm < 2; mm++) {
#pragma unroll
        for (int hh = 0; hh < 2; hh++) {
            int rglb = mtile * 128 + warpM + mm * 16 + gl + hh * 8;
            bool live = (!ROUTED) || (rglb < Me);
            if (!live) continue;
            float w = 1.0f;
            __half* dst;
            if (ROUTED) {
                int slot = start + rglb;
                w = g_slot_w[slot];
                dst = g_hbuf + (size_t)slot * HDIM + (size_t)ntile * 128;
            } else {
                dst = g_sh + (size_t)rglb * HSDIM + (size_t)ntile * 128;
            }
#pragma unroll
            for (int nn = 0; nn < 4; nn++) {
                int c = warpN + nn * 8 + 2 * kl;
                float gv0 = ag[mm][nn][hh * 2], gv1 = ag[mm][nn][hh * 2 + 1];
                float uv0 = au[mm][nn][hh * 2], uv1 = au[mm][nn][hh * 2 + 1];
                __half2 h2 = __floats2half2_rn(silu_f(gv0) * uv0 * w,
                                               silu_f(gv1) * uv1 * w);
                *(__half2*)(dst + c) = h2;
            }
        }
    }
}

// ---------------- down GEMM: mma.sync fp16 + ldmatrix, 3-stage ----------------
template <bool ROUTED>
__global__ __launch_bounds__(512, 1)
void down_mma(const __half* __restrict__ Wd, float* __restrict__ Out) {
    extern __shared__ char smem[];
    constexpr int K = ROUTED ? HDIM : HSDIM;
    constexpr int KT = K / 32;
    uint32_t smA = s2u(smem);

    int tid = threadIdx.x, wid = tid >> 5, lane = tid & 31;
    int warpM = (wid >> 2) * 32, warpN = (wid & 3) * 32;
    int gl = lane >> 2, kl = lane & 3;
    int ntile = blockIdx.x, mtile = blockIdx.y;

    int start = 0, Me = T_TOKENS;
    if (ROUTED) {
        int expert = blockIdx.z;
        start = g_offsets[expert];
        Me = g_offsets[expert + 1] - start;
        if (mtile * 128 >= Me) return;
        Wd += (size_t)expert * HDIM * DIM;
    }
    const __half* Abase = (ROUTED ? g_hbuf : g_sh) + (size_t)(start + mtile * 128) * K;

    int crow = tid >> 2, seg = tid & 3;
    const __half* pA = Abase + (size_t)crow * K + seg * 8;
    const __half* pB = Wd + (size_t)(ntile * 128 + crow) * K + seg * 8;
    uint32_t dOff = smA + (crow * AST + seg * 8) * 2;

#define DN_COPY(stg, kt) do { \
    uint32_t _b = dOff + (stg) * (2 * TILE_B); \
    cp16(_b,          pA + (kt) * 32); \
    cp16(_b + TILE_B, pB + (kt) * 32); \
    cp_commit(); \
} while (0)

    int l8 = lane & 7, lj = lane >> 3;
    uint32_t offA = (uint32_t)((warpM + (lj & 1) * 8 + l8) * AST + (lj >> 1) * 8) * 2;
    uint32_t offB = (uint32_t)((warpN + (lj >> 1) * 8 + l8) * AST + (lj & 1) * 8) * 2;

    float acc[2][4][4];
#pragma unroll
    for (int mm = 0; mm < 2; mm++)
#pragma unroll
        for (int nn = 0; nn < 4; nn++)
#pragma unroll
            for (int q = 0; q < 4; q++) acc[mm][nn][q] = 0.f;

    DN_COPY(0, 0);
    DN_COPY(1, 1);
    for (int kt = 0; kt < KT; kt++) {
        int cur = kt % 3;
        if (kt + 1 < KT) asm volatile("cp.async.wait_group 1;" ::: "memory");
        else             asm volatile("cp.async.wait_group 0;" ::: "memory");
        __syncthreads();
        if (kt + 2 < KT) DN_COPY((kt + 2) % 3, kt + 2);
        uint32_t base = smA + cur * (2 * TILE_B);
#pragma unroll
        for (int ks = 0; ks < 2; ks++) {
            uint32_t a0[4], a1[4], b0[4], b1[4];
            ldsm4(a0, base + offA + ks * 32);
            ldsm4(a1, base + offA + 1280 + ks * 32);
            ldsm4(b0, base + TILE_B + offB + ks * 32);
            ldsm4(b1, base + TILE_B + offB + 1280 + ks * 32);
#pragma unroll
            for (int mm = 0; mm < 2; mm++) {
                const uint32_t* a = mm ? a1 : a0;
                mma16(acc[mm][0], a, b0);
                mma16(acc[mm][1], a, b0 + 2);
                mma16(acc[mm][2], a, b1);
                mma16(acc[mm][3], a, b1 + 2);
            }
        }
    }

#pragma unroll
    for (int mm = 0; mm < 2; mm++) {
#pragma unroll
        for (int hh = 0; hh < 2; hh++) {
            int rglb = mtile * 128 + warpM + mm * 16 + gl + hh * 8;
            bool live = (!ROUTED) || (rglb < Me);
            if (!live) continue;
            float* dst;
            if (ROUTED) {
                int token = g_slot_token[start + rglb];
                dst = Out + (size_t)token * DIM + (size_t)ntile * 128;
            } else {
                dst = Out + (size_t)rglb * DIM + (size_t)ntile * 128;
            }
#pragma unroll
            for (int nn = 0; nn < 4; nn++) {
                int c = warpN + nn * 8 + 2 * kl;
                float v0 = acc[mm][nn][hh * 2], v1 = acc[mm][nn][hh * 2 + 1];
                if (ROUTED) {
                    atomicAdd(dst + c, v0);
                    atomicAdd(dst + c + 1, v1);
                } else {
                    float2 v; v.x = v0; v.y = v1;
                    *(float2*)(dst + c) = v;
                }
            }
        }
    }
}

// ---------------- launch ----------------
extern "C" void kernel_launch(void* const* d_in, const int* in_sizes, int n_in,
                              void* d_out, int out_size) {
    const float* x   = (const float*)d_in[0];
    const float* rw  = (const float*)d_in[1];
    const float* wg  = (const float*)d_in[2];
    const float* wu  = (const float*)d_in[3];
    const float* wd  = (const float*)d_in[4];
    const float* swg = (const float*)d_in[5];
    const float* swu = (const float*)d_in[6];
    const float* swd = (const float*)d_in[7];
    float* out = (float*)d_out;

    // lazy host-object init (first call is the non-captured correctness run)
    static cudaStream_t s1 = nullptr;
    static cudaEvent_t evFork = nullptr, evS = nullptr, evGU = nullptr, evD = nullptr;
    if (s1 == nullptr) {
        cudaStreamCreateWithFlags(&s1, cudaStreamNonBlocking);
        cudaEventCreateWithFlags(&evFork, cudaEventDisableTiming);
        cudaEventCreateWithFlags(&evS, cudaEventDisableTiming);
        cudaEventCreateWithFlags(&evGU, cudaEventDisableTiming);
        cudaEventCreateWithFlags(&evD, cudaEventDisableTiming);
        cudaFuncSetAttribute(gateup_mma<false>, cudaFuncAttributeMaxDynamicSharedMemorySize, GU_SMEM);
        cudaFuncSetAttribute(gateup_mma<true>,  cudaFuncAttributeMaxDynamicSharedMemorySize, GU_SMEM);
        cudaFuncSetAttribute(down_mma<false>,   cudaFuncAttributeMaxDynamicSharedMemorySize, DN_SMEM);
        cudaFuncSetAttribute(down_mma<true>,    cudaFuncAttributeMaxDynamicSharedMemorySize, DN_SMEM);
    }

    __half *wgh, *wuh, *wdh, *swgh, *swuh, *swdh;
    cudaGetSymbolAddress((void**)&wgh, g_wgh);
    cudaGetSymbolAddress((void**)&wuh, g_wuh);
    cudaGetSymbolAddress((void**)&wdh, g_wdh);
    cudaGetSymbolAddress((void**)&swgh, g_swgh);
    cudaGetSymbolAddress((void**)&swuh, g_swuh);
    cudaGetSymbolAddress((void**)&swdh, g_swdh);

    // fork: weight conversions on s1, routing chain on the main stream
    cudaEventRecord(evFork, 0);
    cudaStreamWaitEvent(s1, evFork, 0);
    convw_t_kernel<<<dim3(HSDIM / 32, DIM / 32, 1), dim3(32, 8), 0, s1>>>(swg, swgh, DIM, HSDIM);
    convw_t_kernel<<<dim3(HSDIM / 32, DIM / 32, 1), dim3(32, 8), 0, s1>>>(swu, swuh, DIM, HSDIM);
    cudaEventRecord(evS, s1);
    convw_t_kernel<<<dim3(HDIM / 32, DIM / 32, NEXP), dim3(32, 8), 0, s1>>>(wg, wgh, DIM, HDIM);
    convw_t_kernel<<<dim3(HDIM / 32, DIM / 32, NEXP), dim3(32, 8), 0, s1>>>(wu, wuh, DIM, HDIM);
    cudaEventRecord(evGU, s1);
    convw_t_kernel<<<dim3(DIM / 32, HDIM / 32, NEXP), dim3(32, 8), 0, s1>>>(wd, wdh, HDIM, DIM);
    convw_t_kernel<<<dim3(DIM / 32, HSDIM / 32, 1), dim3(32, 8), 0, s1>>>(swd, swdh, HSDIM, DIM);
    cudaEventRecord(evD, s1);

    // main stream: routing + activation conversion
    zero_small_kernel<<<1, 32>>>();
    router_kernel<<<T_TOKENS / 8, 256>>>(x, rw);
    scan_kernel<<<1, 32>>>();
    scatter_kernel<<<NSLOTS / 256, 256>>>();
    conv_x_kernel<<<T_TOKENS, 256>>>(x);

    // GEMMs, gated on the conversions they consume
    cudaStreamWaitEvent(0, evS, 0);
    gateup_mma<false><<<dim3(HSDIM / 128, T_TOKENS / 128, 1), 512, GU_SMEM>>>(swgh, swuh);
    cudaStreamWaitEvent(0, evGU, 0);
    gateup_mma<true><<<dim3(HDIM / 128, NSLOTS / 128, NEXP), 512, GU_SMEM>>>(wgh, wuh);
    cudaStreamWaitEvent(0, evD, 0);
    down_mma<false><<<dim3(DIM / 128, T_TOKENS / 128, 1), 512, DN_SMEM>>>(swdh, out);
    down_mma<true><<<dim3(DIM / 128, NSLOTS / 128, NEXP), 512, DN_SMEM>>>(wdh, out);
}

// round 13
// speedup vs baseline: 6.1953x; 1.0663x over previous
#include <cuda_runtime.h>
#include <cuda_fp16.h>
#include <cstdint>

#define T_TOKENS 4096
#define DIM      2048
#define NEXP     8
#define HDIM     1024
#define HSDIM    2048
#define NSLOTS   8192
#define PAD      128

// ---------------- scratch (device globals; no allocation allowed) ----------------
__device__ __half g_xr[(size_t)T_TOKENS * DIM];          // fp16 dense x
__device__ __half g_hbuf[(size_t)(NSLOTS + PAD) * HDIM]; // routed h (weight-folded)
__device__ __half g_sh[(size_t)T_TOKENS * HSDIM];        // shared-expert h
__device__ __half g_wgh[(size_t)NEXP * DIM * HDIM];      // transposed [e][n=h][k=d] fp16
__device__ __half g_wuh[(size_t)NEXP * DIM * HDIM];
__device__ __half g_wdh[(size_t)NEXP * HDIM * DIM];      // [e][n=d][k=h]
__device__ __half g_swgh[(size_t)DIM * HSDIM];           // [n=hs][k=d]
__device__ __half g_swuh[(size_t)DIM * HSDIM];
__device__ __half g_swdh[(size_t)HSDIM * DIM];           // [n=d][k=hs]
__device__ int   g_slot_token[NSLOTS];
__device__ float g_slot_w[NSLOTS];
__device__ int   g_counts[NEXP];
__device__ int   g_fill[NEXP];
__device__ int   g_offsets[NEXP + 1];
__device__ int   g_eidx[NSLOTS];
__device__ float g_topw[NSLOTS];

// ---------------- helpers ----------------
__device__ __forceinline__ float silu_f(float g) {
    return g * (1.0f / (1.0f + __expf(-g)));
}
__device__ __forceinline__ uint32_t s2u(const void* p) {
    uint32_t a;
    asm("{ .reg .u64 t; cvta.to.shared.u64 t, %1; cvt.u32.u64 %0, t; }" : "=r"(a) : "l"(p));
    return a;
}
__device__ __forceinline__ void cp16(uint32_t s, const void* g) {
    asm volatile("cp.async.cg.shared.global [%0], [%1], 16;" :: "r"(s), "l"(g));
}
__device__ __forceinline__ void cp_commit() {
    asm volatile("cp.async.commit_group;" ::: "memory");
}
__device__ __forceinline__ void mma16(float* c, const uint32_t* a, const uint32_t* b) {
    asm volatile("mma.sync.aligned.m16n8k16.row.col.f32.f16.f16.f32 "
        "{%0,%1,%2,%3}, {%4,%5,%6,%7}, {%8,%9}, {%0,%1,%2,%3};"
        : "+f"(c[0]), "+f"(c[1]), "+f"(c[2]), "+f"(c[3])
        : "r"(a[0]), "r"(a[1]), "r"(a[2]), "r"(a[3]), "r"(b[0]), "r"(b[1]));
}
__device__ __forceinline__ void ldsm4(uint32_t* d, uint32_t addr) {
    asm volatile("ldmatrix.sync.aligned.m8n8.x4.shared.b16 {%0,%1,%2,%3}, [%4];"
        : "=r"(d[0]), "=r"(d[1]), "=r"(d[2]), "=r"(d[3]) : "r"(addr));
}

// SMEM geometry: every tile (A or B) = 128 rows x 40 halves (32 data + 8 pad)
#define AST 40
#define TILE_B 10240                       // bytes per tile
#define GU_SMEM (3 * 3 * TILE_B)           // 92160 (3 stages x {A,Bg,Bu})
#define DN_SMEM (3 * 2 * TILE_B)           // 61440 (3 stages x {A,B})

// ---------------- routing kernels ----------------
__global__ void zero_small_kernel() {
    int i = threadIdx.x;
    if (i < NEXP) { g_counts[i] = 0; g_fill[i] = 0; }
}

__global__ void router_kernel(const float* __restrict__ x, const float* __restrict__ rw) {
    int t = (blockIdx.x * blockDim.x + threadIdx.x) >> 5;
    int lane = threadIdx.x & 31;
    if (t >= T_TOKENS) return;
    const float* xr = x + (size_t)t * DIM;
    float lg[NEXP];
#pragma unroll
    for (int e = 0; e < NEXP; e++) lg[e] = 0.f;
    for (int d = lane; d < DIM; d += 32) {
        float xv = xr[d];
        const float* r = rw + (size_t)d * NEXP;
#pragma unroll
        for (int e = 0; e < NEXP; e++) lg[e] += xv * r[e];
    }
#pragma unroll
    for (int e = 0; e < NEXP; e++) {
#pragma unroll
        for (int o = 16; o; o >>= 1) lg[e] += __shfl_xor_sync(0xffffffffu, lg[e], o);
    }
    if (lane == 0) {
        float mx = lg[0];
#pragma unroll
        for (int e = 1; e < NEXP; e++) mx = fmaxf(mx, lg[e]);
        float p[NEXP];
#pragma unroll
        for (int e = 0; e < NEXP; e++) p[e] = __expf(lg[e] - mx);
        int i1 = 0;
#pragma unroll
        for (int e = 1; e < NEXP; e++) if (p[e] > p[i1]) i1 = e;
        int i2 = (i1 == 0) ? 1 : 0;
#pragma unroll
        for (int e = 0; e < NEXP; e++) if (e != i1 && p[e] > p[i2]) i2 = e;
        float w1 = p[i1], w2 = p[i2];
        float s = w1 + w2;
        w1 /= s; w2 /= s;
        g_eidx[2 * t] = i1; g_eidx[2 * t + 1] = i2;
        g_topw[2 * t] = w1; g_topw[2 * t + 1] = w2;
        atomicAdd(&g_counts[i1], 1);
        atomicAdd(&g_counts[i2], 1);
    }
}

__global__ void scan_kernel() {
    if (threadIdx.x == 0) {
        int acc = 0;
        for (int e = 0; e < NEXP; e++) { g_offsets[e] = acc; acc += g_counts[e]; }
        g_offsets[NEXP] = acc;
    }
}

__global__ void scatter_kernel() {
    int i = blockIdx.x * blockDim.x + threadIdx.x;
    if (i >= NSLOTS) return;
    int e = g_eidx[i];
    int pos = g_offsets[e] + atomicAdd(&g_fill[e], 1);
    g_slot_token[pos] = i >> 1;
    g_slot_w[pos] = g_topw[i];
}

// ---------------- weight fp32 [K][N] -> fp16 transposed [N][K] ----------------
__global__ void convw_t_kernel(const float* __restrict__ src, __half* __restrict__ dst,
                               int K, int N) {
    __shared__ float t[32][33];
    size_t boff = (size_t)blockIdx.z * K * N;
    const float* ip = src + boff;
    __half* op = dst + boff;
    int c0 = blockIdx.x * 32;  // N dim
    int r0 = blockIdx.y * 32;  // K dim
    int x = threadIdx.x, y = threadIdx.y;
#pragma unroll
    for (int i = 0; i < 32; i += 8)
        t[y + i][x] = ip[(size_t)(r0 + y + i) * N + (c0 + x)];
    __syncthreads();
    int tid = y * 32 + x;
#pragma unroll
    for (int q = 0; q < 2; q++) {
        int p = tid * 2 + q;
        int nl = p >> 4, kc = p & 15;
        __half2 h2 = __floats2half2_rn(t[2 * kc][nl], t[2 * kc + 1][nl]);
        *(__half2*)(op + (size_t)(c0 + nl) * K + r0 + 2 * kc) = h2;
    }
}

// dense fp32 -> fp16 activation conversion
__global__ void conv_x_kernel(const float* __restrict__ x) {
    int r = blockIdx.x;
    int c0 = threadIdx.x * 8;
    const float* src = x + (size_t)r * DIM;
    float4 v0 = *(const float4*)(src + c0);
    float4 v1 = *(const float4*)(src + c0 + 4);
    __half h[8];
    h[0] = __float2half(v0.x); h[1] = __float2half(v0.y);
    h[2] = __float2half(v0.z); h[3] = __float2half(v0.w);
    h[4] = __float2half(v1.x); h[5] = __float2half(v1.y);
    h[6] = __float2half(v1.z); h[7] = __float2half(v1.w);
    *(uint4*)(g_xr + (size_t)r * DIM + c0) = *(uint4*)h;
}

// ---------------- fused gate/up GEMM: mma.sync fp16 + ldmatrix, 3-stage ----------------
// Block 128x128, BK=32, 512 threads (16 warps 4x4), warp tile 32x32.
// ROUTED: A rows gathered inline from g_xr via g_slot_token.
template <bool ROUTED>
__global__ __launch_bounds__(512, 1)
void gateup_mma(const __half* __restrict__ Wg, const __half* __restrict__ Wu) {
    extern __shared__ char smem[];
    constexpr int KT = DIM / 32;  // 64
    uint32_t smA = s2u(smem);

    int tid = threadIdx.x, wid = tid >> 5, lane = tid & 31;
    int warpM = (wid >> 2) * 32, warpN = (wid & 3) * 32;
    int gl = lane >> 2, kl = lane & 3;
    int ntile = blockIdx.x, mtile = blockIdx.y;

    int start = 0, Me = T_TOKENS;
    if (ROUTED) {
        int expert = blockIdx.z;
        start = g_offsets[expert];
        Me = g_offsets[expert + 1] - start;
        if (mtile * 128 >= Me) return;
        Wg += (size_t)expert * DIM * HDIM;
        Wu += (size_t)expert * DIM * HDIM;
    }

    // cp.async lanes: row = tid/4 (0..127), seg = tid%4 (16B each)
    int crow = tid >> 2, seg = tid & 3;
    const __half* pA;
    if (ROUTED) {
        int rr = mtile * 128 + crow;
        if (rr >= Me) rr = Me - 1;                     // clamp; epilogue masks
        pA = g_xr + (size_t)g_slot_token[start + rr] * DIM + seg * 8;
    } else {
        pA = g_xr + (size_t)(mtile * 128 + crow) * DIM + seg * 8;
    }
    const __half* pG = Wg + (size_t)(ntile * 128 + crow) * DIM + seg * 8;
    const __half* pU = Wu + (size_t)(ntile * 128 + crow) * DIM + seg * 8;
    uint32_t dOff = smA + (crow * AST + seg * 8) * 2;

#define GU_COPY(stg, kt) do { \
    uint32_t _b = dOff + (stg) * (3 * TILE_B); \
    cp16(_b,              pA + (kt) * 32); \
    cp16(_b + TILE_B,     pG + (kt) * 32); \
    cp16(_b + 2 * TILE_B, pU + (kt) * 32); \
    cp_commit(); \
} while (0)

    // ldmatrix lane offsets (bytes within a tile)
    int l8 = lane & 7, lj = lane >> 3;
    uint32_t offA = (uint32_t)((warpM + (lj & 1) * 8 + l8) * AST + (lj >> 1) * 8) * 2;
    uint32_t offB = (uint32_t)((warpN + (lj >> 1) * 8 + l8) * AST + (lj & 1) * 8) * 2;

    float ag[2][4][4], au[2][4][4];
#pragma unroll
    for (int mm = 0; mm < 2; mm++)
#pragma unroll
        for (int nn = 0; nn < 4; nn++)
#pragma unroll
            for (int q = 0; q < 4; q++) { ag[mm][nn][q] = 0.f; au[mm][nn][q] = 0.f; }

    GU_COPY(0, 0);
    GU_COPY(1, 1);
    for (int kt = 0; kt < KT; kt++) {
        int cur = kt % 3;
        // wait for this tile's copies (own), then barrier => all threads' copies visible
        if (kt + 1 < KT) asm volatile("cp.async.wait_group 1;" ::: "memory");
        else             asm volatile("cp.async.wait_group 0;" ::: "memory");
        __syncthreads();
        // issue prefetch AFTER barrier: target buffer's last readers are done
        if (kt + 2 < KT) GU_COPY((kt + 2) % 3, kt + 2);
        uint32_t base = smA + cur * (3 * TILE_B);
#pragma unroll
        for (int ks = 0; ks < 2; ks++) {
            uint32_t a0[4], a1[4], bg0[4], bg1[4], bu0[4], bu1[4];
            ldsm4(a0, base + offA + ks * 32);
            ldsm4(a1, base + offA + 1280 + ks * 32);
            ldsm4(bg0, base + TILE_B + offB + ks * 32);
            ldsm4(bg1, base + TILE_B + offB + 1280 + ks * 32);
            ldsm4(bu0, base + 2 * TILE_B + offB + ks * 32);
            ldsm4(bu1, base + 2 * TILE_B + offB + 1280 + ks * 32);
#pragma unroll
            for (int mm = 0; mm < 2; mm++) {
                const uint32_t* a = mm ? a1 : a0;
                mma16(ag[mm][0], a, bg0);
                mma16(ag[mm][1], a, bg0 + 2);
                mma16(ag[mm][2], a, bg1);
                mma16(ag[mm][3], a, bg1 + 2);
                mma16(au[mm][0], a, bu0);
                mma16(au[mm][1], a, bu0 + 2);
                mma16(au[mm][2], a, bu1);
                mma16(au[mm][3], a, bu1 + 2);
            }
        }
    }

    // epilogue: h = half(silu(g)*u*w)
#pragma unroll
    for (int mm = 0; mm < 2; mm++) {
#pragma unroll
        for (int hh = 0; hh < 2; hh++) {
            int rglb = mtile * 128 + warpM + mm * 16 + gl + hh * 8;
            bool live = (!ROUTED) || (rglb < Me);
            if (!live) continue;
            float w = 1.0f;
            __half* dst;
            if (ROUTED) {
                int slot = start + rglb;
                w = g_slot_w[slot];
                dst = g_hbuf + (size_t)slot * HDIM + (size_t)ntile * 128;
            } else {
                dst = g_sh + (size_t)rglb * HSDIM + (size_t)ntile * 128;
            }
#pragma unroll
            for (int nn = 0; nn < 4; nn++) {
                int c = warpN + nn * 8 + 2 * kl;
                float gv0 = ag[mm][nn][hh * 2], gv1 = ag[mm][nn][hh * 2 + 1];
                float uv0 = au[mm][nn][hh * 2], uv1 = au[mm][nn][hh * 2 + 1];
                __half2 h2 = __floats2half2_rn(silu_f(gv0) * uv0 * w,
                                               silu_f(gv1) * uv1 * w);
                *(__half2*)(dst + c) = h2;
            }
        }
    }
}

// ---------------- down GEMM: mma.sync fp16 + ldmatrix, 3-stage ----------------
template <bool ROUTED>
__global__ __launch_bounds__(512, 1)
void down_mma(const __half* __restrict__ Wd, float* __restrict__ Out) {
    extern __shared__ char smem[];
    constexpr int K = ROUTED ? HDIM : HSDIM;
    constexpr int KT = K / 32;
    uint32_t smA = s2u(smem);

    int tid = threadIdx.x, wid = tid >> 5, lane = tid & 31;
    int warpM = (wid >> 2) * 32, warpN = (wid & 3) * 32;
    int gl = lane >> 2, kl = lane & 3;
    int ntile = blockIdx.x, mtile = blockIdx.y;

    int start = 0, Me = T_TOKENS;
    if (ROUTED) {
        int expert = blockIdx.z;
        start = g_offsets[expert];
        Me = g_offsets[expert + 1] - start;
        if (mtile * 128 >= Me) return;
        Wd += (size_t)expert * HDIM * DIM;
    }
    const __half* Abase = (ROUTED ? g_hbuf : g_sh) + (size_t)(start + mtile * 128) * K;

    int crow = tid >> 2, seg = tid & 3;
    const __half* pA = Abase + (size_t)crow * K + seg * 8;
    const __half* pB = Wd + (size_t)(ntile * 128 + crow) * K + seg * 8;
    uint32_t dOff = smA + (crow * AST + seg * 8) * 2;

#define DN_COPY(stg, kt) do { \
    uint32_t _b = dOff + (stg) * (2 * TILE_B); \
    cp16(_b,          pA + (kt) * 32); \
    cp16(_b + TILE_B, pB + (kt) * 32); \
    cp_commit(); \
} while (0)

    int l8 = lane & 7, lj = lane >> 3;
    uint32_t offA = (uint32_t)((warpM + (lj & 1) * 8 + l8) * AST + (lj >> 1) * 8) * 2;
    uint32_t offB = (uint32_t)((warpN + (lj >> 1) * 8 + l8) * AST + (lj & 1) * 8) * 2;

    float acc[2][4][4];
#pragma unroll
    for (int mm = 0; mm < 2; mm++)
#pragma unroll
        for (int nn = 0; nn < 4; nn++)
#pragma unroll
            for (int q = 0; q < 4; q++) acc[mm][nn][q] = 0.f;

    DN_COPY(0, 0);
    DN_COPY(1, 1);
    for (int kt = 0; kt < KT; kt++) {
        int cur = kt % 3;
        if (kt + 1 < KT) asm volatile("cp.async.wait_group 1;" ::: "memory");
        else             asm volatile("cp.async.wait_group 0;" ::: "memory");
        __syncthreads();
        if (kt + 2 < KT) DN_COPY((kt + 2) % 3, kt + 2);
        uint32_t base = smA + cur * (2 * TILE_B);
#pragma unroll
        for (int ks = 0; ks < 2; ks++) {
            uint32_t a0[4], a1[4], b0[4], b1[4];
            ldsm4(a0, base + offA + ks * 32);
            ldsm4(a1, base + offA + 1280 + ks * 32);
            ldsm4(b0, base + TILE_B + offB + ks * 32);
            ldsm4(b1, base + TILE_B + offB + 1280 + ks * 32);
#pragma unroll
            for (int mm = 0; mm < 2; mm++) {
                const uint32_t* a = mm ? a1 : a0;
                mma16(acc[mm][0], a, b0);
                mma16(acc[mm][1], a, b0 + 2);
                mma16(acc[mm][2], a, b1);
                mma16(acc[mm][3], a, b1 + 2);
            }
        }
    }

#pragma unroll
    for (int mm = 0; mm < 2; mm++) {
#pragma unroll
        for (int hh = 0; hh < 2; hh++) {
            int rglb = mtile * 128 + warpM + mm * 16 + gl + hh * 8;
            bool live = (!ROUTED) || (rglb < Me);
            if (!live) continue;
            float* dst;
            if (ROUTED) {
                int token = g_slot_token[start + rglb];
                dst = Out + (size_t)token * DIM + (size_t)ntile * 128;
            } else {
                dst = Out + (size_t)rglb * DIM + (size_t)ntile * 128;
            }
#pragma unroll
            for (int nn = 0; nn < 4; nn++) {
                int c = warpN + nn * 8 + 2 * kl;
                float v0 = acc[mm][nn][hh * 2], v1 = acc[mm][nn][hh * 2 + 1];
                if (ROUTED) {
                    atomicAdd(dst + c, v0);
                    atomicAdd(dst + c + 1, v1);
                } else {
                    float2 v; v.x = v0; v.y = v1;
                    *(float2*)(dst + c) = v;
                }
            }
        }
    }
}

// ---------------- launch ----------------
extern "C" void kernel_launch(void* const* d_in, const int* in_sizes, int n_in,
                              void* d_out, int out_size) {
    const float* x   = (const float*)d_in[0];
    const float* rw  = (const float*)d_in[1];
    const float* wg  = (const float*)d_in[2];
    const float* wu  = (const float*)d_in[3];
    const float* wd  = (const float*)d_in[4];
    const float* swg = (const float*)d_in[5];
    const float* swu = (const float*)d_in[6];
    const float* swd = (const float*)d_in[7];
    float* out = (float*)d_out;

    // lazy host-object init (first call is the non-captured correctness run)
    static cudaStream_t s1 = nullptr, s2 = nullptr;
    static cudaEvent_t evFork = nullptr, evS = nullptr, evGU = nullptr;
    static cudaEvent_t evSD = nullptr, evWD = nullptr, evRoute = nullptr, evRG = nullptr;
    if (s1 == nullptr) {
        cudaStreamCreateWithFlags(&s1, cudaStreamNonBlocking);
        cudaStreamCreateWithFlags(&s2, cudaStreamNonBlocking);
        cudaEventCreateWithFlags(&evFork, cudaEventDisableTiming);
        cudaEventCreateWithFlags(&evS, cudaEventDisableTiming);
        cudaEventCreateWithFlags(&evGU, cudaEventDisableTiming);
        cudaEventCreateWithFlags(&evSD, cudaEventDisableTiming);
        cudaEventCreateWithFlags(&evWD, cudaEventDisableTiming);
        cudaEventCreateWithFlags(&evRoute, cudaEventDisableTiming);
        cudaEventCreateWithFlags(&evRG, cudaEventDisableTiming);
        cudaFuncSetAttribute(gateup_mma<false>, cudaFuncAttributeMaxDynamicSharedMemorySize, GU_SMEM);
        cudaFuncSetAttribute(gateup_mma<true>,  cudaFuncAttributeMaxDynamicSharedMemorySize, GU_SMEM);
        cudaFuncSetAttribute(down_mma<false>,   cudaFuncAttributeMaxDynamicSharedMemorySize, DN_SMEM);
        cudaFuncSetAttribute(down_mma<true>,    cudaFuncAttributeMaxDynamicSharedMemorySize, DN_SMEM);
    }

    __half *wgh, *wuh, *wdh, *swgh, *swuh, *swdh;
    cudaGetSymbolAddress((void**)&wgh, g_wgh);
    cudaGetSymbolAddress((void**)&wuh, g_wuh);
    cudaGetSymbolAddress((void**)&wdh, g_wdh);
    cudaGetSymbolAddress((void**)&swgh, g_swgh);
    cudaGetSymbolAddress((void**)&swuh, g_swuh);
    cudaGetSymbolAddress((void**)&swdh, g_swdh);

    // fork: weight conversions on s1 in consumption order
    cudaEventRecord(evFork, 0);
    cudaStreamWaitEvent(s1, evFork, 0);
    cudaStreamWaitEvent(s2, evFork, 0);
    convw_t_kernel<<<dim3(HSDIM / 32, DIM / 32, 1), dim3(32, 8), 0, s1>>>(swg, swgh, DIM, HSDIM);
    convw_t_kernel<<<dim3(HSDIM / 32, DIM / 32, 1), dim3(32, 8), 0, s1>>>(swu, swuh, DIM, HSDIM);
    cudaEventRecord(evS, s1);
    convw_t_kernel<<<dim3(HDIM / 32, DIM / 32, NEXP), dim3(32, 8), 0, s1>>>(wg, wgh, DIM, HDIM);
    convw_t_kernel<<<dim3(HDIM / 32, DIM / 32, NEXP), dim3(32, 8), 0, s1>>>(wu, wuh, DIM, HDIM);
    cudaEventRecord(evGU, s1);
    convw_t_kernel<<<dim3(DIM / 32, HSDIM / 32, 1), dim3(32, 8), 0, s1>>>(swd, swdh, HSDIM, DIM);
    cudaEventRecord(evSD, s1);
    convw_t_kernel<<<dim3(DIM / 32, HDIM / 32, NEXP), dim3(32, 8), 0, s1>>>(wd, wdh, HDIM, DIM);
    cudaEventRecord(evWD, s1);

    // main stream: routing + activation conversion
    zero_small_kernel<<<1, 32>>>();
    router_kernel<<<T_TOKENS / 8, 256>>>(x, rw);
    scan_kernel<<<1, 32>>>();
    scatter_kernel<<<NSLOTS / 256, 256>>>();
    conv_x_kernel<<<T_TOKENS, 256>>>(x);
    cudaEventRecord(evRoute, 0);

    // s2: routed gate/up, overlapping the shared chain on main
    cudaStreamWaitEvent(s2, evRoute, 0);
    cudaStreamWaitEvent(s2, evGU, 0);
    gateup_mma<true><<<dim3(HDIM / 128, NSLOTS / 128, NEXP), 512, GU_SMEM, s2>>>(wgh, wuh);
    cudaEventRecord(evRG, s2);

    // main: shared chain, then routed down (after shared-down's init stores + evRG)
    cudaStreamWaitEvent(0, evS, 0);
    gateup_mma<false><<<dim3(HSDIM / 128, T_TOKENS / 128, 1), 512, GU_SMEM>>>(swgh, swuh);
    cudaStreamWaitEvent(0, evSD, 0);
    down_mma<false><<<dim3(DIM / 128, T_TOKENS / 128, 1), 512, DN_SMEM>>>(swdh, out);
    cudaStreamWaitEvent(0, evRG, 0);
    cudaStreamWaitEvent(0, evWD, 0);
    down_mma<true><<<dim3(DIM / 128, NSLOTS / 128, NEXP), 512, DN_SMEM>>>(wdh, out);
}